// round 1
// baseline (speedup 1.0000x reference)
#include <cuda_runtime.h>

#define NN 100000
#define EE 1600000
#define GG 2048
#define HD 64

// ---------------- scratch (device globals, no allocation) ----------------
__device__ float    g_hA[NN * HD];     // layer input / output features
__device__ float    g_hw[NN * HD];     // linear output of current layer
__device__ float    g_acc[NN * HD];    // aggregation accumulator
__device__ float    g_deg[NN];         // in-degree + 1 (self loop)
__device__ float    g_dinv[NN];        // rsqrt(deg)
__device__ float    g_den[NN];         // softmax denominator
__device__ unsigned g_amax[NN];        // encoded segment max
__device__ float    g_as[NN], g_ad[NN];
__device__ float    g_aself[NN];       // self-loop leaky score
__device__ float    g_self1[NN], g_self2[NN];   // self-loop edge-score (per GAT layer)
__device__ float    g_es1[EE], g_es2[EE];       // per-edge edge-attr scores
__device__ float    g_aedge[EE];                // per-edge leaky score
__device__ unsigned g_pool[GG * HD];            // encoded max-pool
__device__ float    g_v[32];                    // We1@ae1 (0..15), We2@ae2 (16..31)

// monotone float<->uint encoding for atomicMax on floats
__device__ __forceinline__ unsigned encf(float f) {
    unsigned u = __float_as_uint(f);
    return (u & 0x80000000u) ? ~u : (u | 0x80000000u);
}
__device__ __forceinline__ float decf(unsigned u) {
    return __uint_as_float((u & 0x80000000u) ? (u & 0x7fffffffu) : ~u);
}
#define ENC_NEGINF 0x007fffffu   // encf(-inf)

// ---------------- kernels ----------------

__global__ void k_init() {
    int i = blockIdx.x * blockDim.x + threadIdx.x;
    if (i < NN) { g_deg[i] = 1.0f; g_self1[i] = 0.0f; g_self2[i] = 0.0f; }
}

__global__ void k_vecs(const float* __restrict__ We1, const float* __restrict__ ae1,
                       const float* __restrict__ We2, const float* __restrict__ ae2) {
    int t = threadIdx.x;
    if (t >= 32) return;
    const float* We = (t < 16) ? We1 : We2;
    const float* ae = (t < 16) ? ae1 : ae2;
    int j = t & 15;
    float s = 0.f;
    #pragma unroll 8
    for (int c = 0; c < HD; c++) s += We[j * HD + c] * ae[c];
    g_v[t] = s;
}

__global__ void k_deg(const int* __restrict__ dst) {
    int i = blockIdx.x * blockDim.x + threadIdx.x;
    if (i < EE) atomicAdd(&g_deg[dst[i]], 1.0f);
}

__global__ void k_dinv() {
    int i = blockIdx.x * blockDim.x + threadIdx.x;
    if (i < NN) g_dinv[i] = rsqrtf(g_deg[i]);
}

__global__ void k_escore(const float* __restrict__ ea, const int* __restrict__ dst) {
    int i = blockIdx.x * blockDim.x + threadIdx.x;
    if (i >= EE) return;
    const float4* p = (const float4*)(ea + (size_t)i * 16);
    float e[16];
    #pragma unroll
    for (int k = 0; k < 4; k++) {
        float4 q = p[k];
        e[4*k] = q.x; e[4*k+1] = q.y; e[4*k+2] = q.z; e[4*k+3] = q.w;
    }
    float s1 = 0.f, s2 = 0.f;
    #pragma unroll
    for (int k = 0; k < 16; k++) { s1 += e[k] * g_v[k]; s2 += e[k] * g_v[16 + k]; }
    g_es1[i] = s1; g_es2[i] = s2;
    int d = dst[i];
    atomicAdd(&g_self1[d], s1);
    atomicAdd(&g_self2[d], s2);
}

__global__ void k_selfdiv() {
    int i = blockIdx.x * blockDim.x + threadIdx.x;
    if (i >= NN) return;
    float c = fmaxf(g_deg[i] - 1.0f, 1.0f);
    g_self1[i] /= c; g_self2[i] /= c;
}

// tiled GEMM: out[N,64] = X[N,KD] @ W[KD,64]; also zeroes g_acc
template <int KD>
__global__ void k_gemm(const float* __restrict__ Xext, const float* __restrict__ W,
                       int useInternal) {
    const float* X = useInternal ? g_hA : Xext;
    __shared__ float Ws[KD * 64];
    __shared__ float Xs[16][KD + 1];
    for (int i = threadIdx.x; i < KD * 64; i += 256) Ws[i] = W[i];
    int node0 = blockIdx.x * 16;
    for (int i = threadIdx.x; i < 16 * KD; i += 256) {
        int r = i / KD, k = i % KD;
        Xs[r][k] = X[(size_t)(node0 + r) * KD + k];
    }
    __syncthreads();
    int c  = threadIdx.x & 63;
    int r0 = (threadIdx.x >> 6) * 4;
    float s0 = 0.f, s1 = 0.f, s2 = 0.f, s3 = 0.f;
    #pragma unroll
    for (int k = 0; k < KD; k++) {
        float w = Ws[k * 64 + c];
        s0 += Xs[r0    ][k] * w;
        s1 += Xs[r0 + 1][k] * w;
        s2 += Xs[r0 + 2][k] * w;
        s3 += Xs[r0 + 3][k] * w;
    }
    size_t base = (size_t)(node0 + r0) * 64 + c;
    g_hw[base]        = s0; g_acc[base]        = 0.f;
    g_hw[base + 64]   = s1; g_acc[base + 64]   = 0.f;
    g_hw[base + 128]  = s2; g_acc[base + 128]  = 0.f;
    g_hw[base + 192]  = s3; g_acc[base + 192]  = 0.f;
}

// per-node attention dots + init amax/den; one warp per node
__global__ void k_attprep(const float* __restrict__ att_s, const float* __restrict__ att_d) {
    int gid  = blockIdx.x * blockDim.x + threadIdx.x;
    int node = gid >> 5;
    int lane = gid & 31;
    if (node >= NN) return;
    float h0 = g_hw[(size_t)node * 64 + lane];
    float h1 = g_hw[(size_t)node * 64 + 32 + lane];
    float s = h0 * att_s[lane] + h1 * att_s[lane + 32];
    float d = h0 * att_d[lane] + h1 * att_d[lane + 32];
    #pragma unroll
    for (int o = 16; o; o >>= 1) {
        s += __shfl_down_sync(0xffffffffu, s, o);
        d += __shfl_down_sync(0xffffffffu, d, o);
    }
    if (lane == 0) {
        g_as[node] = s; g_ad[node] = d;
        g_amax[node] = ENC_NEGINF; g_den[node] = 0.f;
    }
}

__global__ void k_attmax(const int* __restrict__ src, const int* __restrict__ dst, int layer) {
    int i = blockIdx.x * blockDim.x + threadIdx.x;
    if (i >= EE + NN) return;
    const float* es   = (layer == 1) ? g_es1   : g_es2;
    const float* self = (layer == 1) ? g_self1 : g_self2;
    float a; int d;
    if (i < EE) {
        int s = src[i]; d = dst[i];
        a = g_as[s] + g_ad[d] + es[i];
    } else {
        int n = i - EE; d = n;
        a = g_as[n] + g_ad[n] + self[n];
    }
    a = (a > 0.f) ? a : 0.2f * a;
    if (i < EE) g_aedge[i] = a; else g_aself[d] = a;
    atomicMax(&g_amax[d], encf(a));
}

// fused exp + den + weighted aggregation; 8 threads/edge, float4 vector atomics
__global__ void k_gat_agg(const int* __restrict__ src, const int* __restrict__ dst) {
    long long gid = (long long)blockIdx.x * blockDim.x + threadIdx.x;
    int e = (int)(gid >> 3);
    int p = (int)(gid & 7);
    if (e >= EE + NN) return;
    int s, d; float ex;
    if (e < EE) {
        s = src[e]; d = dst[e];
        ex = __expf(g_aedge[e] - decf(g_amax[d]));
    } else {
        s = d = e - EE;
        ex = __expf(g_aself[s] - decf(g_amax[s]));
    }
    if (p == 0) atomicAdd(&g_den[d], ex);
    const float4* hs = (const float4*)(g_hw + (size_t)s * 64) + p * 2;
    float4 A = hs[0], B = hs[1];
    A.x *= ex; A.y *= ex; A.z *= ex; A.w *= ex;
    B.x *= ex; B.y *= ex; B.z *= ex; B.w *= ex;
    float4* ac = (float4*)(g_acc + (size_t)d * 64) + p * 2;
    atomicAdd(ac,     A);
    atomicAdd(ac + 1, B);
}

__global__ void k_gcn_agg(const int* __restrict__ src, const int* __restrict__ dst) {
    long long gid = (long long)blockIdx.x * blockDim.x + threadIdx.x;
    int e = (int)(gid >> 3);
    int p = (int)(gid & 7);
    if (e >= EE) return;
    int s = src[e], d = dst[e];
    float c = g_dinv[s] * g_dinv[d];
    const float4* hs = (const float4*)(g_hw + (size_t)s * 64) + p * 2;
    float4 A = hs[0], B = hs[1];
    A.x *= c; A.y *= c; A.z *= c; A.w *= c;
    B.x *= c; B.y *= c; B.z *= c; B.w *= c;
    float4* ac = (float4*)(g_acc + (size_t)d * 64) + p * 2;
    atomicAdd(ac,     A);
    atomicAdd(ac + 1, B);
}

__global__ void k_gcn_fin(const float* __restrict__ b) {
    int gid = blockIdx.x * blockDim.x + threadIdx.x;
    if (gid >= NN * HD) return;
    int n = gid >> 6, c = gid & 63;
    float di = g_dinv[n];
    float v = g_acc[gid] + g_hw[gid] * di * di + b[c];
    g_hA[gid] = fmaxf(v, 0.f);
}

__global__ void k_gat_fin(const float* __restrict__ b) {
    int gid = blockIdx.x * blockDim.x + threadIdx.x;
    if (gid >= NN * HD) return;
    int n = gid >> 6, c = gid & 63;
    float v = g_acc[gid] / g_den[n] + b[c];
    g_hA[gid] = fmaxf(v, 0.f);
}

__global__ void k_poolinit() {
    int i = blockIdx.x * blockDim.x + threadIdx.x;
    if (i < GG * HD) g_pool[i] = ENC_NEGINF;
}

__global__ void k_pool(const int* __restrict__ batch) {
    int gid = blockIdx.x * blockDim.x + threadIdx.x;
    if (gid >= NN * HD) return;
    int n = gid >> 6, c = gid & 63;
    int g = batch[n];
    atomicMax(&g_pool[g * 64 + c], encf(g_hA[gid]));
}

__global__ void k_fc(const float* __restrict__ W1, const float* __restrict__ b1,
                     const float* __restrict__ W2, const float* __restrict__ b2,
                     float* __restrict__ out) {
    __shared__ float t0[64], t1[64];
    int g = blockIdx.x, c = threadIdx.x;
    t0[c] = decf(g_pool[g * 64 + c]);
    __syncthreads();
    float s = 0.f;
    #pragma unroll 8
    for (int k = 0; k < 64; k++) s += t0[k] * W1[k * 64 + c];
    t1[c] = fmaxf(s + b1[c], 0.f);
    __syncthreads();
    float o = 0.f;
    #pragma unroll 8
    for (int k = 0; k < 64; k++) o += t1[k] * W2[k * 64 + c];
    out[g * 64 + c] = o + b2[c];
}

// ---------------- launch ----------------
extern "C" void kernel_launch(void* const* d_in, const int* in_sizes, int n_in,
                              void* d_out, int out_size) {
    const float* x     = (const float*)d_in[0];
    const int*   ei    = (const int*)  d_in[1];
    const float* ea    = (const float*)d_in[2];
    const int*   batch = (const int*)  d_in[3];
    const float* W_gcn = (const float*)d_in[4];
    const float* b_gcn = (const float*)d_in[5];
    const float* W1    = (const float*)d_in[6];
    const float* We1   = (const float*)d_in[7];
    const float* as1   = (const float*)d_in[8];
    const float* ad1   = (const float*)d_in[9];
    const float* ae1   = (const float*)d_in[10];
    const float* b1    = (const float*)d_in[11];
    const float* W2    = (const float*)d_in[12];
    const float* We2   = (const float*)d_in[13];
    const float* as2   = (const float*)d_in[14];
    const float* ad2   = (const float*)d_in[15];
    const float* ae2   = (const float*)d_in[16];
    const float* b2    = (const float*)d_in[17];
    const float* Wf1   = (const float*)d_in[18];
    const float* bf1   = (const float*)d_in[19];
    const float* Wf2   = (const float*)d_in[20];
    const float* bf2   = (const float*)d_in[21];
    float* out = (float*)d_out;

    const int* src = ei;
    const int* dst = ei + EE;

    const int TB = 256;
    const int gN    = (NN + TB - 1) / TB;            // 391
    const int gE    = (EE + TB - 1) / TB;            // 6250
    const int gEN   = (EE + NN + TB - 1) / TB;       // 6641
    const int gE8   = (EE * 8) / TB;                 // 50000
    const int gEN8  = ((EE + NN) * 8) / TB;          // 53125
    const int gNH   = (NN * HD) / TB;                // 25000
    const int gGemm = NN / 16;                        // 6250

    k_init<<<gN, TB>>>();
    k_vecs<<<1, 32>>>(We1, ae1, We2, ae2);
    k_deg<<<gE, TB>>>(dst);
    k_dinv<<<gN, TB>>>();
    k_escore<<<gE, TB>>>(ea, dst);
    k_selfdiv<<<gN, TB>>>();

    // GCN
    k_gemm<128><<<gGemm, TB>>>(x, W_gcn, 0);
    k_gcn_agg<<<gE8, TB>>>(src, dst);
    k_gcn_fin<<<gNH, TB>>>(b_gcn);

    // GAT 1
    k_gemm<64><<<gGemm, TB>>>(nullptr, W1, 1);
    k_attprep<<<(NN * 32 + TB - 1) / TB, TB>>>(as1, ad1);
    k_attmax<<<gEN, TB>>>(src, dst, 1);
    k_gat_agg<<<gEN8, TB>>>(src, dst);
    k_gat_fin<<<gNH, TB>>>(b1);

    // GAT 2
    k_gemm<64><<<gGemm, TB>>>(nullptr, W2, 1);
    k_attprep<<<(NN * 32 + TB - 1) / TB, TB>>>(as2, ad2);
    k_attmax<<<gEN, TB>>>(src, dst, 2);
    k_gat_agg<<<gEN8, TB>>>(src, dst);
    k_gat_fin<<<gNH, TB>>>(b2);

    // pool + MLP head
    k_poolinit<<<(GG * HD + TB - 1) / TB, TB>>>();
    k_pool<<<gNH, TB>>>(batch);
    k_fc<<<GG, 64>>>(Wf1, bf1, Wf2, bf2, out);
}

// round 2
// speedup vs baseline: 1.0455x; 1.0455x over previous
#include <cuda_runtime.h>

#define NN 100000
#define EE 1600000
#define GG 2048
#define HD 64

// ---------------- scratch (device globals) ----------------
__device__ float    g_hA[NN * HD];     // layer activation
__device__ float    g_hw[NN * HD];     // linear output (GCN: pre-scaled by dinv[src])
__device__ float    g_acc[NN * HD];    // aggregation accumulator
__device__ float    g_deg[NN];
__device__ float    g_dinv[NN];
__device__ float    g_den[NN];         // softmax denominator
__device__ float    g_as[NN], g_ad[NN];
__device__ float    g_self1[NN], g_self2[NN];   // self-loop edge scores
__device__ float    g_es1[EE], g_es2[EE];       // per-edge edge-attr scores
__device__ unsigned g_pool[GG * HD];
__device__ float    g_v[32];                    // We1@ae1 | We2@ae2

__device__ __forceinline__ unsigned encf(float f) {
    unsigned u = __float_as_uint(f);
    return (u & 0x80000000u) ? ~u : (u | 0x80000000u);
}
__device__ __forceinline__ float decf(unsigned u) {
    return __uint_as_float((u & 0x80000000u) ? (u & 0x7fffffffu) : ~u);
}
#define ENC_NEGINF 0x007fffffu

// ---------------- kernels ----------------

__global__ void k_init() {
    int i = blockIdx.x * blockDim.x + threadIdx.x;
    if (i < NN) { g_deg[i] = 1.0f; g_self1[i] = 0.0f; g_self2[i] = 0.0f; }
}

__global__ void k_vecs(const float* __restrict__ We1, const float* __restrict__ ae1,
                       const float* __restrict__ We2, const float* __restrict__ ae2) {
    int t = threadIdx.x;
    if (t >= 32) return;
    const float* We = (t < 16) ? We1 : We2;
    const float* ae = (t < 16) ? ae1 : ae2;
    int j = t & 15;
    float s = 0.f;
    #pragma unroll 8
    for (int c = 0; c < HD; c++) s += We[j * HD + c] * ae[c];
    g_v[t] = s;
}

// edge-attr scores + degree + self-loop score sums (one edge pass)
__global__ void k_escore(const float* __restrict__ ea, const int* __restrict__ dst) {
    int i = blockIdx.x * blockDim.x + threadIdx.x;
    if (i >= EE) return;
    const float4* p = (const float4*)(ea + (size_t)i * 16);
    float e[16];
    #pragma unroll
    for (int k = 0; k < 4; k++) {
        float4 q = p[k];
        e[4*k] = q.x; e[4*k+1] = q.y; e[4*k+2] = q.z; e[4*k+3] = q.w;
    }
    float s1 = 0.f, s2 = 0.f;
    #pragma unroll
    for (int k = 0; k < 16; k++) { s1 += e[k] * g_v[k]; s2 += e[k] * g_v[16 + k]; }
    g_es1[i] = s1; g_es2[i] = s2;
    int d = dst[i];
    atomicAdd(&g_deg[d], 1.0f);
    atomicAdd(&g_self1[d], s1);
    atomicAdd(&g_self2[d], s2);
}

// dinv + self-loop mean division (fused node pass)
__global__ void k_post() {
    int i = blockIdx.x * blockDim.x + threadIdx.x;
    if (i >= NN) return;
    float deg = g_deg[i];
    g_dinv[i] = rsqrtf(deg);
    float c = fmaxf(deg - 1.0f, 1.0f);
    g_self1[i] /= c; g_self2[i] /= c;
}

// tiled GEMM: hw[N,64] = X[N,KD] @ W[KD,64]; zeroes g_acc.
// MODE 0 (GCN): hw pre-scaled by dinv[row].
// MODE 1 (GAT): epilogue computes a_s/a_d per node (shuffle reduction), zeroes den.
template <int KD, int MODE>
__global__ void k_gemm(const float* __restrict__ Xext, const float* __restrict__ W,
                       const float* __restrict__ att_s, const float* __restrict__ att_d,
                       int useInternal) {
    const float* X = useInternal ? g_hA : Xext;
    __shared__ float Ws[KD * 64];
    __shared__ float Xs[16][KD + 1];
    __shared__ float sred[16], dred[16];
    for (int i = threadIdx.x; i < KD * 64; i += 256) Ws[i] = W[i];
    int node0 = blockIdx.x * 16;
    for (int i = threadIdx.x; i < 16 * KD; i += 256) {
        int r = i / KD, k = i % KD;
        Xs[r][k] = X[(size_t)(node0 + r) * KD + k];
    }
    if (MODE == 1 && threadIdx.x < 16) { sred[threadIdx.x] = 0.f; dred[threadIdx.x] = 0.f; }
    __syncthreads();
    int c  = threadIdx.x & 63;
    int r0 = (threadIdx.x >> 6) * 4;
    float s0 = 0.f, s1 = 0.f, s2 = 0.f, s3 = 0.f;
    #pragma unroll
    for (int k = 0; k < KD; k++) {
        float w = Ws[k * 64 + c];
        s0 += Xs[r0    ][k] * w;
        s1 += Xs[r0 + 1][k] * w;
        s2 += Xs[r0 + 2][k] * w;
        s3 += Xs[r0 + 3][k] * w;
    }
    size_t base = (size_t)(node0 + r0) * 64 + c;
    if (MODE == 0) {
        float d0 = g_dinv[node0 + r0],     d1 = g_dinv[node0 + r0 + 1];
        float d2 = g_dinv[node0 + r0 + 2], d3 = g_dinv[node0 + r0 + 3];
        g_hw[base]       = s0 * d0; g_acc[base]       = 0.f;
        g_hw[base + 64]  = s1 * d1; g_acc[base + 64]  = 0.f;
        g_hw[base + 128] = s2 * d2; g_acc[base + 128] = 0.f;
        g_hw[base + 192] = s3 * d3; g_acc[base + 192] = 0.f;
    } else {
        g_hw[base]       = s0; g_acc[base]       = 0.f;
        g_hw[base + 64]  = s1; g_acc[base + 64]  = 0.f;
        g_hw[base + 128] = s2; g_acc[base + 128] = 0.f;
        g_hw[base + 192] = s3; g_acc[base + 192] = 0.f;
        float av = att_s[c], dv = att_d[c];
        float ps0 = s0 * av, ps1 = s1 * av, ps2 = s2 * av, ps3 = s3 * av;
        float pd0 = s0 * dv, pd1 = s1 * dv, pd2 = s2 * dv, pd3 = s3 * dv;
        #pragma unroll
        for (int o = 16; o; o >>= 1) {
            ps0 += __shfl_down_sync(0xffffffffu, ps0, o);
            ps1 += __shfl_down_sync(0xffffffffu, ps1, o);
            ps2 += __shfl_down_sync(0xffffffffu, ps2, o);
            ps3 += __shfl_down_sync(0xffffffffu, ps3, o);
            pd0 += __shfl_down_sync(0xffffffffu, pd0, o);
            pd1 += __shfl_down_sync(0xffffffffu, pd1, o);
            pd2 += __shfl_down_sync(0xffffffffu, pd2, o);
            pd3 += __shfl_down_sync(0xffffffffu, pd3, o);
        }
        if ((threadIdx.x & 31) == 0) {
            atomicAdd(&sred[r0],     ps0); atomicAdd(&sred[r0 + 1], ps1);
            atomicAdd(&sred[r0 + 2], ps2); atomicAdd(&sred[r0 + 3], ps3);
            atomicAdd(&dred[r0],     pd0); atomicAdd(&dred[r0 + 1], pd1);
            atomicAdd(&dred[r0 + 2], pd2); atomicAdd(&dred[r0 + 3], pd3);
        }
        __syncthreads();
        if (threadIdx.x < 16) {
            g_as[node0 + threadIdx.x]  = sred[threadIdx.x];
            g_ad[node0 + threadIdx.x]  = dred[threadIdx.x];
            g_den[node0 + threadIdx.x] = 0.f;
        }
    }
}

// GCN aggregation: acc[d] += hw_scaled[s]; zero per-edge scalars
__global__ void k_gcn_agg(const int* __restrict__ src, const int* __restrict__ dst) {
    int gid = blockIdx.x * blockDim.x + threadIdx.x;   // < 12.8M
    int e = gid >> 3;
    int p = gid & 7;
    int s = src[e], d = dst[e];
    const float4* hs = (const float4*)(g_hw + (size_t)s * 64) + p * 2;
    float4 A = hs[0], B = hs[1];
    float4* ac = (float4*)(g_acc + (size_t)d * 64) + p * 2;
    atomicAdd(ac,     A);
    atomicAdd(ac + 1, B);
}

// fused GAT edge pass: score -> leaky -> exp -> den + weighted aggregation
// warp handles 4 edges (8 lanes/edge); group leader computes exp, shfl-broadcast
__global__ void k_gat_agg(const int* __restrict__ src, const int* __restrict__ dst, int layer) {
    int gid  = blockIdx.x * blockDim.x + threadIdx.x;  // < 13.6M
    int lane = threadIdx.x & 31;
    int e    = (gid >> 5) * 4 + (lane >> 3);
    int sub  = lane & 7;
    int s, d;
    if (e < EE) { s = src[e]; d = dst[e]; }
    else        { s = d = e - EE; }
    float ex = 0.f;
    if (sub == 0) {
        float a;
        if (e < EE) a = g_as[s] + g_ad[d] + ((layer == 1) ? g_es1[e]   : g_es2[e]);
        else        a = g_as[s] + g_ad[s] + ((layer == 1) ? g_self1[s] : g_self2[s]);
        a = (a > 0.f) ? a : 0.2f * a;
        ex = __expf(a);
        atomicAdd(&g_den[d], ex);
    }
    ex = __shfl_sync(0xffffffffu, ex, lane & 0x18);
    const float4* hs = (const float4*)(g_hw + (size_t)s * 64) + sub * 2;
    float4 A = hs[0], B = hs[1];
    A.x *= ex; A.y *= ex; A.z *= ex; A.w *= ex;
    B.x *= ex; B.y *= ex; B.z *= ex; B.w *= ex;
    float4* ac = (float4*)(g_acc + (size_t)d * 64) + sub * 2;
    atomicAdd(ac,     A);
    atomicAdd(ac + 1, B);
}

__global__ void k_gcn_fin(const float* __restrict__ b) {
    int gid = blockIdx.x * blockDim.x + threadIdx.x;
    if (gid >= NN * HD) return;
    int n = gid >> 6, c = gid & 63;
    float v = (g_acc[gid] + g_hw[gid]) * g_dinv[n] + b[c];
    g_hA[gid] = fmaxf(v, 0.f);
}

__global__ void k_gat_fin(const float* __restrict__ b) {
    int gid = blockIdx.x * blockDim.x + threadIdx.x;
    if (gid >= NN * HD) return;
    int n = gid >> 6, c = gid & 63;
    float v = g_acc[gid] / g_den[n] + b[c];
    g_hA[gid] = fmaxf(v, 0.f);
}

__global__ void k_poolinit() {
    int i = blockIdx.x * blockDim.x + threadIdx.x;
    if (i < GG * HD) g_pool[i] = ENC_NEGINF;
}

__global__ void k_pool(const int* __restrict__ batch) {
    int gid = blockIdx.x * blockDim.x + threadIdx.x;
    if (gid >= NN * HD) return;
    int n = gid >> 6, c = gid & 63;
    int g = batch[n];
    atomicMax(&g_pool[g * 64 + c], encf(g_hA[gid]));
}

__global__ void k_fc(const float* __restrict__ W1, const float* __restrict__ b1,
                     const float* __restrict__ W2, const float* __restrict__ b2,
                     float* __restrict__ out) {
    __shared__ float t0[64], t1[64];
    int g = blockIdx.x, c = threadIdx.x;
    t0[c] = decf(g_pool[g * 64 + c]);
    __syncthreads();
    float s = 0.f;
    #pragma unroll 8
    for (int k = 0; k < 64; k++) s += t0[k] * W1[k * 64 + c];
    t1[c] = fmaxf(s + b1[c], 0.f);
    __syncthreads();
    float o = 0.f;
    #pragma unroll 8
    for (int k = 0; k < 64; k++) o += t1[k] * W2[k * 64 + c];
    out[g * 64 + c] = o + b2[c];
}

// ---------------- launch ----------------
extern "C" void kernel_launch(void* const* d_in, const int* in_sizes, int n_in,
                              void* d_out, int out_size) {
    const float* x     = (const float*)d_in[0];
    const int*   ei    = (const int*)  d_in[1];
    const float* ea    = (const float*)d_in[2];
    const int*   batch = (const int*)  d_in[3];
    const float* W_gcn = (const float*)d_in[4];
    const float* b_gcn = (const float*)d_in[5];
    const float* W1    = (const float*)d_in[6];
    const float* We1   = (const float*)d_in[7];
    const float* as1   = (const float*)d_in[8];
    const float* ad1   = (const float*)d_in[9];
    const float* ae1   = (const float*)d_in[10];
    const float* b1    = (const float*)d_in[11];
    const float* W2    = (const float*)d_in[12];
    const float* We2   = (const float*)d_in[13];
    const float* as2   = (const float*)d_in[14];
    const float* ad2   = (const float*)d_in[15];
    const float* ae2   = (const float*)d_in[16];
    const float* b2    = (const float*)d_in[17];
    const float* Wf1   = (const float*)d_in[18];
    const float* bf1   = (const float*)d_in[19];
    const float* Wf2   = (const float*)d_in[20];
    const float* bf2   = (const float*)d_in[21];
    float* out = (float*)d_out;

    const int* src = ei;
    const int* dst = ei + EE;

    const int TB = 256;
    const int gN    = (NN + TB - 1) / TB;
    const int gE    = (EE + TB - 1) / TB;
    const int gE8   = (EE * 8) / TB;                 // 50000
    const int gEN8  = ((EE + NN) * 8) / TB;          // 53125 (exact)
    const int gNH   = (NN * HD) / TB;
    const int gGemm = NN / 16;

    k_init<<<gN, TB>>>();
    k_vecs<<<1, 32>>>(We1, ae1, We2, ae2);
    k_escore<<<gE, TB>>>(ea, dst);
    k_post<<<gN, TB>>>();

    // GCN
    k_gemm<128, 0><<<gGemm, TB>>>(x, W_gcn, nullptr, nullptr, 0);
    k_gcn_agg<<<gE8, TB>>>(src, dst);
    k_gcn_fin<<<gNH, TB>>>(b_gcn);

    // GAT 1
    k_gemm<64, 1><<<gGemm, TB>>>(nullptr, W1, as1, ad1, 1);
    k_gat_agg<<<gEN8, TB>>>(src, dst, 1);
    k_gat_fin<<<gNH, TB>>>(b1);

    // GAT 2
    k_gemm<64, 1><<<gGemm, TB>>>(nullptr, W2, as2, ad2, 1);
    k_gat_agg<<<gEN8, TB>>>(src, dst, 2);
    k_gat_fin<<<gNH, TB>>>(b2);

    // pool + MLP head
    k_poolinit<<<(GG * HD + TB - 1) / TB, TB>>>();
    k_pool<<<gNH, TB>>>(batch);
    k_fc<<<GG, 64>>>(Wf1, bf1, Wf2, bf2, out);
}

// round 3
// speedup vs baseline: 1.5689x; 1.5006x over previous
#include <cuda_runtime.h>

#define NN 100000
#define EE 1600000
#define GG 2048
#define HD 64
#define SCAN_B 1024
#define SCAN_G ((NN + SCAN_B - 1) / SCAN_B)   // 98

// ---------------- scratch ----------------
__device__ float  g_hA[NN * HD];
__device__ float  g_hw[NN * HD];
__device__ float  g_dinv[NN];
__device__ float  g_as[NN], g_ad[NN];
__device__ int    g_cnt[NN];
__device__ int    g_rs[NN + 1];
__device__ int    g_cur[NN];
__device__ int    g_bsum[SCAN_G], g_boff[SCAN_G];
__device__ float4 c_pack[EE];        // CSR-ordered: (src, es1, es2, 0)
__device__ unsigned g_pool[GG * HD];
__device__ float  g_v[32];

__device__ __forceinline__ unsigned encf(float f) {
    unsigned u = __float_as_uint(f);
    return (u & 0x80000000u) ? ~u : (u | 0x80000000u);
}
__device__ __forceinline__ float decf(unsigned u) {
    return __uint_as_float((u & 0x80000000u) ? (u & 0x7fffffffu) : ~u);
}
#define ENC_NEGINF 0x007fffffu

// ---------------- kernels ----------------

__global__ void k_zero() {
    int i = blockIdx.x * blockDim.x + threadIdx.x;
    if (i < NN) g_cnt[i] = 0;
}

__global__ void k_vecs(const float* __restrict__ We1, const float* __restrict__ ae1,
                       const float* __restrict__ We2, const float* __restrict__ ae2) {
    int t = threadIdx.x;
    if (t >= 32) return;
    const float* We = (t < 16) ? We1 : We2;
    const float* ae = (t < 16) ? ae1 : ae2;
    int j = t & 15;
    float s = 0.f;
    #pragma unroll 8
    for (int c = 0; c < HD; c++) s += We[j * HD + c] * ae[c];
    g_v[t] = s;
}

__global__ void k_cnt(const int* __restrict__ dst) {
    int i = blockIdx.x * blockDim.x + threadIdx.x;
    if (i < EE) atomicAdd(&g_cnt[dst[i]], 1);
}

__global__ void k_scan1() {
    __shared__ int sh[SCAN_B];
    int t = threadIdx.x;
    int i = blockIdx.x * SCAN_B + t;
    int v = (i < NN) ? g_cnt[i] : 0;
    sh[t] = v;
    __syncthreads();
    for (int off = 1; off < SCAN_B; off <<= 1) {
        int x = (t >= off) ? sh[t - off] : 0;
        __syncthreads();
        sh[t] += x;
        __syncthreads();
    }
    if (i < NN) g_rs[i] = sh[t] - v;
    if (t == SCAN_B - 1) g_bsum[blockIdx.x] = sh[t];
}

__global__ void k_scan2() {
    if (threadIdx.x == 0) {
        int s = 0;
        for (int b = 0; b < SCAN_G; b++) { g_boff[b] = s; s += g_bsum[b]; }
    }
}

__global__ void k_scan3() {
    int i = blockIdx.x * SCAN_B + threadIdx.x;
    if (i < NN) {
        int rs = g_rs[i] + g_boff[blockIdx.x];
        g_rs[i] = rs;
        g_cur[i] = rs;
        g_dinv[i] = rsqrtf((float)(g_cnt[i] + 1));
    }
    if (i == 0) g_rs[NN] = EE;
}

// edge-attr scores + CSR scatter (one DRAM pass over ea)
__global__ void k_scatter(const float* __restrict__ ea,
                          const int* __restrict__ src, const int* __restrict__ dst) {
    int i = blockIdx.x * blockDim.x + threadIdx.x;
    if (i >= EE) return;
    const float4* p = (const float4*)(ea + (size_t)i * 16);
    float e[16];
    #pragma unroll
    for (int k = 0; k < 4; k++) {
        float4 q = p[k];
        e[4*k] = q.x; e[4*k+1] = q.y; e[4*k+2] = q.z; e[4*k+3] = q.w;
    }
    float s1 = 0.f, s2 = 0.f;
    #pragma unroll
    for (int k = 0; k < 16; k++) { s1 += e[k] * g_v[k]; s2 += e[k] * g_v[16 + k]; }
    int d = dst[i];
    int pos = atomicAdd(&g_cur[d], 1);
    c_pack[pos] = make_float4(__int_as_float(src[i]), s1, s2, 0.f);
}

// tiled GEMM: hw[N,64] = X[N,KD] @ W[KD,64]
// MODE 0 (GCN): pre-scale rows by dinv.  MODE 1 (GAT): epilogue a_s/a_d.
template <int KD, int MODE>
__global__ void k_gemm(const float* __restrict__ Xext, const float* __restrict__ W,
                       const float* __restrict__ att_s, const float* __restrict__ att_d,
                       int useInternal) {
    const float* X = useInternal ? g_hA : Xext;
    __shared__ float Ws[KD * 64];
    __shared__ float Xs[16][KD + 1];
    __shared__ float sred[16], dred[16];
    for (int i = threadIdx.x; i < KD * 64; i += 256) Ws[i] = W[i];
    int node0 = blockIdx.x * 16;
    for (int i = threadIdx.x; i < 16 * KD; i += 256) {
        int r = i / KD, k = i % KD;
        Xs[r][k] = X[(size_t)(node0 + r) * KD + k];
    }
    if (MODE == 1 && threadIdx.x < 16) { sred[threadIdx.x] = 0.f; dred[threadIdx.x] = 0.f; }
    __syncthreads();
    int c  = threadIdx.x & 63;
    int r0 = (threadIdx.x >> 6) * 4;
    float s0 = 0.f, s1 = 0.f, s2 = 0.f, s3 = 0.f;
    #pragma unroll
    for (int k = 0; k < KD; k++) {
        float w = Ws[k * 64 + c];
        s0 += Xs[r0    ][k] * w;
        s1 += Xs[r0 + 1][k] * w;
        s2 += Xs[r0 + 2][k] * w;
        s3 += Xs[r0 + 3][k] * w;
    }
    size_t base = (size_t)(node0 + r0) * 64 + c;
    if (MODE == 0) {
        g_hw[base]       = s0 * g_dinv[node0 + r0];
        g_hw[base + 64]  = s1 * g_dinv[node0 + r0 + 1];
        g_hw[base + 128] = s2 * g_dinv[node0 + r0 + 2];
        g_hw[base + 192] = s3 * g_dinv[node0 + r0 + 3];
    } else {
        g_hw[base]       = s0;
        g_hw[base + 64]  = s1;
        g_hw[base + 128] = s2;
        g_hw[base + 192] = s3;
        float av = att_s[c], dv = att_d[c];
        float ps0 = s0 * av, ps1 = s1 * av, ps2 = s2 * av, ps3 = s3 * av;
        float pd0 = s0 * dv, pd1 = s1 * dv, pd2 = s2 * dv, pd3 = s3 * dv;
        #pragma unroll
        for (int o = 16; o; o >>= 1) {
            ps0 += __shfl_down_sync(0xffffffffu, ps0, o);
            ps1 += __shfl_down_sync(0xffffffffu, ps1, o);
            ps2 += __shfl_down_sync(0xffffffffu, ps2, o);
            ps3 += __shfl_down_sync(0xffffffffu, ps3, o);
            pd0 += __shfl_down_sync(0xffffffffu, pd0, o);
            pd1 += __shfl_down_sync(0xffffffffu, pd1, o);
            pd2 += __shfl_down_sync(0xffffffffu, pd2, o);
            pd3 += __shfl_down_sync(0xffffffffu, pd3, o);
        }
        if ((threadIdx.x & 31) == 0) {
            atomicAdd(&sred[r0],     ps0); atomicAdd(&sred[r0 + 1], ps1);
            atomicAdd(&sred[r0 + 2], ps2); atomicAdd(&sred[r0 + 3], ps3);
            atomicAdd(&dred[r0],     pd0); atomicAdd(&dred[r0 + 1], pd1);
            atomicAdd(&dred[r0 + 2], pd2); atomicAdd(&dred[r0 + 3], pd3);
        }
        __syncthreads();
        if (threadIdx.x < 16) {
            g_as[node0 + threadIdx.x] = sred[threadIdx.x];
            g_ad[node0 + threadIdx.x] = dred[threadIdx.x];
        }
    }
}

// GCN gather: warp per node, no atomics, fused bias+relu
__global__ void k_gcn_node(const float* __restrict__ b) {
    int node = blockIdx.x * 8 + (threadIdx.x >> 5);
    int lane = threadIdx.x & 31;
    if (node >= NN) return;
    int rs = g_rs[node], re = g_rs[node + 1];
    float a0 = 0.f, a1 = 0.f;
    for (int j = rs; j < re; j++) {
        float4 pk = c_pack[j];
        int s = __float_as_int(pk.x);
        a0 += g_hw[(size_t)s * 64 + lane];
        a1 += g_hw[(size_t)s * 64 + 32 + lane];
    }
    a0 += g_hw[(size_t)node * 64 + lane];
    a1 += g_hw[(size_t)node * 64 + 32 + lane];
    float di = g_dinv[node];
    g_hA[(size_t)node * 64 + lane]      = fmaxf(a0 * di + b[lane], 0.f);
    g_hA[(size_t)node * 64 + 32 + lane] = fmaxf(a1 * di + b[lane + 32], 0.f);
}

// GAT gather: warp per node; score->exp->den + weighted sum + self loop + fin
template <int LAYER>
__global__ void k_gat_node(const float* __restrict__ b) {
    int node = blockIdx.x * 8 + (threadIdx.x >> 5);
    int lane = threadIdx.x & 31;
    if (node >= NN) return;
    int rs = g_rs[node], re = g_rs[node + 1];
    float ad_n = g_ad[node];
    float a0 = 0.f, a1 = 0.f, den = 0.f, sum_es = 0.f;
    for (int j = rs; j < re; j++) {
        float4 pk = c_pack[j];
        int s = __float_as_int(pk.x);
        float es = (LAYER == 1) ? pk.y : pk.z;
        float a = g_as[s] + ad_n + es;
        a = (a > 0.f) ? a : 0.2f * a;
        float ex = __expf(a);
        sum_es += es;
        den += ex;
        a0 += ex * g_hw[(size_t)s * 64 + lane];
        a1 += ex * g_hw[(size_t)s * 64 + 32 + lane];
    }
    // self loop (edge attr = mean of incoming es)
    float cnt = (float)(re - rs);
    float a = g_as[node] + ad_n + sum_es / fmaxf(cnt, 1.f);
    a = (a > 0.f) ? a : 0.2f * a;
    float ex = __expf(a);
    den += ex;
    a0 += ex * g_hw[(size_t)node * 64 + lane];
    a1 += ex * g_hw[(size_t)node * 64 + 32 + lane];
    float inv = 1.f / den;
    g_hA[(size_t)node * 64 + lane]      = fmaxf(a0 * inv + b[lane], 0.f);
    g_hA[(size_t)node * 64 + 32 + lane] = fmaxf(a1 * inv + b[lane + 32], 0.f);
}

__global__ void k_poolinit() {
    int i = blockIdx.x * blockDim.x + threadIdx.x;
    if (i < GG * HD) g_pool[i] = ENC_NEGINF;
}

// segmented pool: thread scans 16 sorted nodes, flushes on graph change
__global__ void k_pool(const int* __restrict__ batch) {
    int c  = threadIdx.x & 63;
    int grp = threadIdx.x >> 6;                  // 0..3
    int n0 = blockIdx.x * 64 + grp * 16;
    if (n0 >= NN) return;
    int curg = batch[n0];
    float m = -3.402823466e+38f;
    for (int k = 0; k < 16; k++) {
        int n = n0 + k;
        if (n >= NN) break;
        int bg = batch[n];
        if (bg != curg) {
            atomicMax(&g_pool[curg * 64 + c], encf(m));
            m = -3.402823466e+38f;
            curg = bg;
        }
        m = fmaxf(m, g_hA[(size_t)n * 64 + c]);
    }
    atomicMax(&g_pool[curg * 64 + c], encf(m));
}

__global__ void k_fc(const float* __restrict__ W1, const float* __restrict__ b1,
                     const float* __restrict__ W2, const float* __restrict__ b2,
                     float* __restrict__ out) {
    __shared__ float t0[64], t1[64];
    int g = blockIdx.x, c = threadIdx.x;
    t0[c] = decf(g_pool[g * 64 + c]);
    __syncthreads();
    float s = 0.f;
    #pragma unroll 8
    for (int k = 0; k < 64; k++) s += t0[k] * W1[k * 64 + c];
    t1[c] = fmaxf(s + b1[c], 0.f);
    __syncthreads();
    float o = 0.f;
    #pragma unroll 8
    for (int k = 0; k < 64; k++) o += t1[k] * W2[k * 64 + c];
    out[g * 64 + c] = o + b2[c];
}

// ---------------- launch ----------------
extern "C" void kernel_launch(void* const* d_in, const int* in_sizes, int n_in,
                              void* d_out, int out_size) {
    const float* x     = (const float*)d_in[0];
    const int*   ei    = (const int*)  d_in[1];
    const float* ea    = (const float*)d_in[2];
    const int*   batch = (const int*)  d_in[3];
    const float* W_gcn = (const float*)d_in[4];
    const float* b_gcn = (const float*)d_in[5];
    const float* W1    = (const float*)d_in[6];
    const float* We1   = (const float*)d_in[7];
    const float* as1   = (const float*)d_in[8];
    const float* ad1   = (const float*)d_in[9];
    const float* ae1   = (const float*)d_in[10];
    const float* b1    = (const float*)d_in[11];
    const float* W2    = (const float*)d_in[12];
    const float* We2   = (const float*)d_in[13];
    const float* as2   = (const float*)d_in[14];
    const float* ad2   = (const float*)d_in[15];
    const float* ae2   = (const float*)d_in[16];
    const float* b2    = (const float*)d_in[17];
    const float* Wf1   = (const float*)d_in[18];
    const float* bf1   = (const float*)d_in[19];
    const float* Wf2   = (const float*)d_in[20];
    const float* bf2   = (const float*)d_in[21];
    float* out = (float*)d_out;

    const int* src = ei;
    const int* dst = ei + EE;

    const int TB = 256;
    const int gN    = (NN + TB - 1) / TB;
    const int gE    = (EE + TB - 1) / TB;
    const int gGemm = NN / 16;
    const int gNode = (NN + 7) / 8;

    k_zero<<<gN, TB>>>();
    k_vecs<<<1, 32>>>(We1, ae1, We2, ae2);
    k_cnt<<<gE, TB>>>(dst);
    k_scan1<<<SCAN_G, SCAN_B>>>();
    k_scan2<<<1, 32>>>();
    k_scan3<<<SCAN_G, SCAN_B>>>();
    k_scatter<<<gE, TB>>>(ea, src, dst);

    // GCN
    k_gemm<128, 0><<<gGemm, TB>>>(x, W_gcn, nullptr, nullptr, 0);
    k_gcn_node<<<gNode, TB>>>(b_gcn);

    // GAT 1
    k_gemm<64, 1><<<gGemm, TB>>>(nullptr, W1, as1, ad1, 1);
    k_gat_node<1><<<gNode, TB>>>(b1);

    // GAT 2
    k_gemm<64, 1><<<gGemm, TB>>>(nullptr, W2, as2, ad2, 1);
    k_gat_node<2><<<gNode, TB>>>(b2);

    // pool + MLP head
    k_poolinit<<<(GG * HD + TB - 1) / TB, TB>>>();
    k_pool<<<(NN + 63) / 64, TB>>>(batch);
    k_fc<<<GG, 64>>>(Wf1, bf1, Wf2, bf2, out);
}

// round 4
// speedup vs baseline: 1.6477x; 1.0502x over previous
#include <cuda_runtime.h>
#include <cuda_fp16.h>

#define NN 100000
#define EE 1600000
#define GG 2048
#define HD 64
#define SCAN_B 1024
#define SCAN_G ((NN + SCAN_B - 1) / SCAN_B)   // 98

// ---------------- scratch ----------------
__device__ float  g_hA[NN * HD];       // fp32 activations (GEMM input)
__device__ __half g_hw[NN * HD];       // fp16 pre-aggregation features
__device__ float  g_dinv[NN];
__device__ float  g_as[NN], g_ad[NN];
__device__ int    g_cnt[NN];
__device__ int    g_rs[NN + 1];
__device__ int    g_cur[NN];
__device__ int    g_bsum[SCAN_G], g_boff[SCAN_G];
__device__ uint2  c_pack[EE];          // CSR-ordered: (src, half2(es1,es2))
__device__ unsigned g_pool[GG * HD];
__device__ float  g_v[32];

__device__ __forceinline__ unsigned encf(float f) {
    unsigned u = __float_as_uint(f);
    return (u & 0x80000000u) ? ~u : (u | 0x80000000u);
}
__device__ __forceinline__ float decf(unsigned u) {
    return __uint_as_float((u & 0x80000000u) ? (u & 0x7fffffffu) : ~u);
}
#define ENC_NEGINF 0x007fffffu

__device__ __forceinline__ float lrelu(float a) { return (a > 0.f) ? a : 0.2f * a; }

// ---------------- setup kernels ----------------

__global__ void k_zero(const float* __restrict__ We1, const float* __restrict__ ae1,
                       const float* __restrict__ We2, const float* __restrict__ ae2) {
    int i = blockIdx.x * blockDim.x + threadIdx.x;
    if (i < NN) g_cnt[i] = 0;
    if (blockIdx.x == 0 && threadIdx.x < 32) {
        int t = threadIdx.x;
        const float* We = (t < 16) ? We1 : We2;
        const float* ae = (t < 16) ? ae1 : ae2;
        int j = t & 15;
        float s = 0.f;
        #pragma unroll 8
        for (int c = 0; c < HD; c++) s += We[j * HD + c] * ae[c];
        g_v[t] = s;
    }
}

__global__ void k_cnt(const int* __restrict__ dst) {
    int i = blockIdx.x * blockDim.x + threadIdx.x;
    if (i < EE) atomicAdd(&g_cnt[dst[i]], 1);
}

__global__ void k_scan1() {
    __shared__ int sh[SCAN_B];
    int t = threadIdx.x;
    int i = blockIdx.x * SCAN_B + t;
    int v = (i < NN) ? g_cnt[i] : 0;
    sh[t] = v;
    __syncthreads();
    for (int off = 1; off < SCAN_B; off <<= 1) {
        int x = (t >= off) ? sh[t - off] : 0;
        __syncthreads();
        sh[t] += x;
        __syncthreads();
    }
    if (i < NN) g_rs[i] = sh[t] - v;
    if (t == SCAN_B - 1) g_bsum[blockIdx.x] = sh[t];
}

__global__ void k_scan2() {
    if (threadIdx.x == 0) {
        int s = 0;
        for (int b = 0; b < SCAN_G; b++) { g_boff[b] = s; s += g_bsum[b]; }
    }
}

__global__ void k_scan3() {
    int i = blockIdx.x * SCAN_B + threadIdx.x;
    if (i < NN) {
        int rs = g_rs[i] + g_boff[blockIdx.x];
        g_rs[i] = rs;
        g_cur[i] = rs;
        g_dinv[i] = rsqrtf((float)(g_cnt[i] + 1));
    }
    if (i == 0) g_rs[NN] = EE;
}

__global__ void k_scatter(const float* __restrict__ ea,
                          const int* __restrict__ src, const int* __restrict__ dst) {
    int i = blockIdx.x * blockDim.x + threadIdx.x;
    if (i >= EE) return;
    const float4* p = (const float4*)(ea + (size_t)i * 16);
    float e[16];
    #pragma unroll
    for (int k = 0; k < 4; k++) {
        float4 q = p[k];
        e[4*k] = q.x; e[4*k+1] = q.y; e[4*k+2] = q.z; e[4*k+3] = q.w;
    }
    float s1 = 0.f, s2 = 0.f;
    #pragma unroll
    for (int k = 0; k < 16; k++) { s1 += e[k] * g_v[k]; s2 += e[k] * g_v[16 + k]; }
    int d = dst[i];
    int pos = atomicAdd(&g_cur[d], 1);
    __half2 h = __floats2half2_rn(s1, s2);
    uint2 pk;
    pk.x = (unsigned)src[i];
    pk.y = *reinterpret_cast<unsigned*>(&h);
    c_pack[pos] = pk;
}

// ---------------- GEMM ----------------
// hw[N,64](fp16) = X[N,KD] @ W[KD,64]
// MODE 0 (GCN): rows pre-scaled by dinv.  MODE 1 (GAT): epilogue a_s/a_d.
template <int KD, int MODE>
__global__ void k_gemm(const float* __restrict__ Xext, const float* __restrict__ W,
                       const float* __restrict__ att_s, const float* __restrict__ att_d,
                       int useInternal) {
    const float* X = useInternal ? g_hA : Xext;
    __shared__ float Ws[KD * 64];
    __shared__ float Xs[16][KD + 1];
    __shared__ float sred[16], dred[16];
    for (int i = threadIdx.x; i < KD * 64; i += 256) Ws[i] = W[i];
    int node0 = blockIdx.x * 16;
    for (int i = threadIdx.x; i < 16 * KD; i += 256) {
        int r = i / KD, k = i % KD;
        Xs[r][k] = X[(size_t)(node0 + r) * KD + k];
    }
    if (MODE == 1 && threadIdx.x < 16) { sred[threadIdx.x] = 0.f; dred[threadIdx.x] = 0.f; }
    __syncthreads();
    int c  = threadIdx.x & 63;
    int r0 = (threadIdx.x >> 6) * 4;
    float s0 = 0.f, s1 = 0.f, s2 = 0.f, s3 = 0.f;
    #pragma unroll
    for (int k = 0; k < KD; k++) {
        float w = Ws[k * 64 + c];
        s0 += Xs[r0    ][k] * w;
        s1 += Xs[r0 + 1][k] * w;
        s2 += Xs[r0 + 2][k] * w;
        s3 += Xs[r0 + 3][k] * w;
    }
    size_t base = (size_t)(node0 + r0) * 64 + c;
    if (MODE == 0) {
        g_hw[base]       = __float2half(s0 * g_dinv[node0 + r0]);
        g_hw[base + 64]  = __float2half(s1 * g_dinv[node0 + r0 + 1]);
        g_hw[base + 128] = __float2half(s2 * g_dinv[node0 + r0 + 2]);
        g_hw[base + 192] = __float2half(s3 * g_dinv[node0 + r0 + 3]);
    } else {
        g_hw[base]       = __float2half(s0);
        g_hw[base + 64]  = __float2half(s1);
        g_hw[base + 128] = __float2half(s2);
        g_hw[base + 192] = __float2half(s3);
        float av = att_s[c], dv = att_d[c];
        float ps0 = s0 * av, ps1 = s1 * av, ps2 = s2 * av, ps3 = s3 * av;
        float pd0 = s0 * dv, pd1 = s1 * dv, pd2 = s2 * dv, pd3 = s3 * dv;
        #pragma unroll
        for (int o = 16; o; o >>= 1) {
            ps0 += __shfl_down_sync(0xffffffffu, ps0, o);
            ps1 += __shfl_down_sync(0xffffffffu, ps1, o);
            ps2 += __shfl_down_sync(0xffffffffu, ps2, o);
            ps3 += __shfl_down_sync(0xffffffffu, ps3, o);
            pd0 += __shfl_down_sync(0xffffffffu, pd0, o);
            pd1 += __shfl_down_sync(0xffffffffu, pd1, o);
            pd2 += __shfl_down_sync(0xffffffffu, pd2, o);
            pd3 += __shfl_down_sync(0xffffffffu, pd3, o);
        }
        if ((threadIdx.x & 31) == 0) {
            atomicAdd(&sred[r0],     ps0); atomicAdd(&sred[r0 + 1], ps1);
            atomicAdd(&sred[r0 + 2], ps2); atomicAdd(&sred[r0 + 3], ps3);
            atomicAdd(&dred[r0],     pd0); atomicAdd(&dred[r0 + 1], pd1);
            atomicAdd(&dred[r0 + 2], pd2); atomicAdd(&dred[r0 + 3], pd3);
        }
        __syncthreads();
        if (threadIdx.x < 16) {
            g_as[node0 + threadIdx.x] = sred[threadIdx.x];
            g_ad[node0 + threadIdx.x] = dred[threadIdx.x];
        }
    }
}

// ---------------- gathers ----------------

__device__ __forceinline__ float2 hwrow(int s, int lane) {
    __half2 v = *((const __half2*)(g_hw + (size_t)s * 64) + lane);
    return __half22float2(v);
}

// GCN: warp per node, 4x unrolled gather
__global__ void k_gcn_node(const float* __restrict__ b) {
    int node = blockIdx.x * 8 + (threadIdx.x >> 5);
    int lane = threadIdx.x & 31;
    if (node >= NN) return;
    int rs = g_rs[node], re = g_rs[node + 1];
    float a0 = 0.f, a1 = 0.f;
    int j = rs;
    for (; j + 4 <= re; j += 4) {
        uint2 q0 = c_pack[j], q1 = c_pack[j+1], q2 = c_pack[j+2], q3 = c_pack[j+3];
        float2 f0 = hwrow((int)q0.x, lane);
        float2 f1 = hwrow((int)q1.x, lane);
        float2 f2 = hwrow((int)q2.x, lane);
        float2 f3 = hwrow((int)q3.x, lane);
        a0 += f0.x + f1.x + f2.x + f3.x;
        a1 += f0.y + f1.y + f2.y + f3.y;
    }
    for (; j < re; j++) {
        float2 f = hwrow((int)c_pack[j].x, lane);
        a0 += f.x; a1 += f.y;
    }
    float2 fs = hwrow(node, lane);
    a0 += fs.x; a1 += fs.y;
    float di = g_dinv[node];
    float2 bb = ((const float2*)b)[lane];
    float2 o;
    o.x = fmaxf(a0 * di + bb.x, 0.f);
    o.y = fmaxf(a1 * di + bb.y, 0.f);
    ((float2*)(g_hA + (size_t)node * 64))[lane] = o;
}

// GAT: warp per node; fused score->exp->den + weighted sum + self loop + fin
template <int LAYER>
__global__ void k_gat_node(const float* __restrict__ b) {
    int node = blockIdx.x * 8 + (threadIdx.x >> 5);
    int lane = threadIdx.x & 31;
    if (node >= NN) return;
    int rs = g_rs[node], re = g_rs[node + 1];
    float ad_n = g_ad[node];
    float a0 = 0.f, a1 = 0.f, den = 0.f, sum_es = 0.f;
    int j = rs;
    for (; j + 4 <= re; j += 4) {
        uint2 q0 = c_pack[j], q1 = c_pack[j+1], q2 = c_pack[j+2], q3 = c_pack[j+3];
        int s0 = (int)q0.x, s1 = (int)q1.x, s2 = (int)q2.x, s3 = (int)q3.x;
        float as0 = g_as[s0], as1 = g_as[s1], as2 = g_as[s2], as3 = g_as[s3];
        float2 f0 = hwrow(s0, lane);
        float2 f1 = hwrow(s1, lane);
        float2 f2 = hwrow(s2, lane);
        float2 f3 = hwrow(s3, lane);
        __half2 h0 = *reinterpret_cast<__half2*>(&q0.y);
        __half2 h1 = *reinterpret_cast<__half2*>(&q1.y);
        __half2 h2 = *reinterpret_cast<__half2*>(&q2.y);
        __half2 h3 = *reinterpret_cast<__half2*>(&q3.y);
        float e0 = (LAYER == 1) ? __low2float(h0) : __high2float(h0);
        float e1 = (LAYER == 1) ? __low2float(h1) : __high2float(h1);
        float e2 = (LAYER == 1) ? __low2float(h2) : __high2float(h2);
        float e3 = (LAYER == 1) ? __low2float(h3) : __high2float(h3);
        float x0 = __expf(lrelu(as0 + ad_n + e0));
        float x1 = __expf(lrelu(as1 + ad_n + e1));
        float x2 = __expf(lrelu(as2 + ad_n + e2));
        float x3 = __expf(lrelu(as3 + ad_n + e3));
        sum_es += (e0 + e1) + (e2 + e3);
        den    += (x0 + x1) + (x2 + x3);
        a0 += x0 * f0.x + x1 * f1.x + x2 * f2.x + x3 * f3.x;
        a1 += x0 * f0.y + x1 * f1.y + x2 * f2.y + x3 * f3.y;
    }
    for (; j < re; j++) {
        uint2 q = c_pack[j];
        int s = (int)q.x;
        float2 f = hwrow(s, lane);
        __half2 h = *reinterpret_cast<__half2*>(&q.y);
        float e = (LAYER == 1) ? __low2float(h) : __high2float(h);
        float x = __expf(lrelu(g_as[s] + ad_n + e));
        sum_es += e; den += x;
        a0 += x * f.x; a1 += x * f.y;
    }
    // self loop: edge attr score = mean of incoming es
    float cnt = (float)(re - rs);
    float x = __expf(lrelu(g_as[node] + ad_n + sum_es / fmaxf(cnt, 1.f)));
    den += x;
    float2 fs = hwrow(node, lane);
    a0 += x * fs.x; a1 += x * fs.y;
    float inv = 1.f / den;
    float2 bb = ((const float2*)b)[lane];
    float2 o;
    o.x = fmaxf(a0 * inv + bb.x, 0.f);
    o.y = fmaxf(a1 * inv + bb.y, 0.f);
    ((float2*)(g_hA + (size_t)node * 64))[lane] = o;
}

// ---------------- pool + head ----------------

__global__ void k_poolinit() {
    int i = blockIdx.x * blockDim.x + threadIdx.x;
    if (i < GG * HD) g_pool[i] = ENC_NEGINF;
}

__global__ void k_pool(const int* __restrict__ batch) {
    int c   = threadIdx.x & 63;
    int grp = threadIdx.x >> 6;
    int n0  = blockIdx.x * 64 + grp * 16;
    if (n0 >= NN) return;
    int curg = batch[n0];
    float m = -3.402823466e+38f;
    for (int k = 0; k < 16; k++) {
        int n = n0 + k;
        if (n >= NN) break;
        int bg = batch[n];
        if (bg != curg) {
            atomicMax(&g_pool[curg * 64 + c], encf(m));
            m = -3.402823466e+38f;
            curg = bg;
        }
        m = fmaxf(m, g_hA[(size_t)n * 64 + c]);
    }
    atomicMax(&g_pool[curg * 64 + c], encf(m));
}

__global__ void k_fc(const float* __restrict__ W1, const float* __restrict__ b1,
                     const float* __restrict__ W2, const float* __restrict__ b2,
                     float* __restrict__ out) {
    __shared__ float t0[64], t1[64];
    int g = blockIdx.x, c = threadIdx.x;
    t0[c] = decf(g_pool[g * 64 + c]);
    __syncthreads();
    float s = 0.f;
    #pragma unroll 8
    for (int k = 0; k < 64; k++) s += t0[k] * W1[k * 64 + c];
    t1[c] = fmaxf(s + b1[c], 0.f);
    __syncthreads();
    float o = 0.f;
    #pragma unroll 8
    for (int k = 0; k < 64; k++) o += t1[k] * W2[k * 64 + c];
    out[g * 64 + c] = o + b2[c];
}

// ---------------- launch ----------------
extern "C" void kernel_launch(void* const* d_in, const int* in_sizes, int n_in,
                              void* d_out, int out_size) {
    const float* x     = (const float*)d_in[0];
    const int*   ei    = (const int*)  d_in[1];
    const float* ea    = (const float*)d_in[2];
    const int*   batch = (const int*)  d_in[3];
    const float* W_gcn = (const float*)d_in[4];
    const float* b_gcn = (const float*)d_in[5];
    const float* W1    = (const float*)d_in[6];
    const float* We1   = (const float*)d_in[7];
    const float* as1   = (const float*)d_in[8];
    const float* ad1   = (const float*)d_in[9];
    const float* ae1   = (const float*)d_in[10];
    const float* b1    = (const float*)d_in[11];
    const float* W2    = (const float*)d_in[12];
    const float* We2   = (const float*)d_in[13];
    const float* as2   = (const float*)d_in[14];
    const float* ad2   = (const float*)d_in[15];
    const float* ae2   = (const float*)d_in[16];
    const float* b2    = (const float*)d_in[17];
    const float* Wf1   = (const float*)d_in[18];
    const float* bf1   = (const float*)d_in[19];
    const float* Wf2   = (const float*)d_in[20];
    const float* bf2   = (const float*)d_in[21];
    float* out = (float*)d_out;

    const int* src = ei;
    const int* dst = ei + EE;

    const int TB = 256;
    const int gN    = (NN + TB - 1) / TB;
    const int gE    = (EE + TB - 1) / TB;
    const int gGemm = NN / 16;
    const int gNode = (NN + 7) / 8;

    k_zero<<<gN, TB>>>(We1, ae1, We2, ae2);
    k_cnt<<<gE, TB>>>(dst);
    k_scan1<<<SCAN_G, SCAN_B>>>();
    k_scan2<<<1, 32>>>();
    k_scan3<<<SCAN_G, SCAN_B>>>();
    k_scatter<<<gE, TB>>>(ea, src, dst);

    // GCN
    k_gemm<128, 0><<<gGemm, TB>>>(x, W_gcn, nullptr, nullptr, 0);
    k_gcn_node<<<gNode, TB>>>(b_gcn);

    // GAT 1
    k_gemm<64, 1><<<gGemm, TB>>>(nullptr, W1, as1, ad1, 1);
    k_gat_node<1><<<gNode, TB>>>(b1);

    // GAT 2
    k_gemm<64, 1><<<gGemm, TB>>>(nullptr, W2, as2, ad2, 1);
    k_gat_node<2><<<gNode, TB>>>(b2);

    // pool + MLP head
    k_poolinit<<<(GG * HD + TB - 1) / TB, TB>>>();
    k_pool<<<(NN + 63) / 64, TB>>>(batch);
    k_fc<<<GG, 64>>>(Wf1, bf1, Wf2, bf2, out);
}

// round 5
// speedup vs baseline: 2.4709x; 1.4996x over previous
#include <cuda_runtime.h>
#include <cuda_fp16.h>

#define NN 100000
#define EE 1600000
#define GG 2048
#define HD 64
#define SCAN_B 1024
#define SCAN_G ((NN + SCAN_B - 1) / SCAN_B)   // 98

// ---------------- scratch ----------------
__device__ float    g_hA[NN * HD];       // fp32 activations (GEMM input)
__device__ __half   g_hw[NN * HD];       // fp16 pre-aggregation features
__device__ float    g_dinv[NN];
__device__ float    g_as[NN], g_ad[NN];
__device__ int      g_cnt[NN];
__device__ int      g_rs[NN + 1];
__device__ int      g_cur[NN];
__device__ int      g_bsum[SCAN_G], g_boff[SCAN_G];
__device__ int      c_src[EE];           // CSR-ordered source ids
__device__ unsigned c_es[EE];            // CSR-ordered half2(es1, es2)
__device__ unsigned g_pool[GG * HD];
__device__ float    g_v[32];

__device__ __forceinline__ unsigned encf(float f) {
    unsigned u = __float_as_uint(f);
    return (u & 0x80000000u) ? ~u : (u | 0x80000000u);
}
__device__ __forceinline__ float decf(unsigned u) {
    return __uint_as_float((u & 0x80000000u) ? (u & 0x7fffffffu) : ~u);
}
#define ENC_NEGINF 0x007fffffu

__device__ __forceinline__ float lrelu(float a) { return (a > 0.f) ? a : 0.2f * a; }

// ---------------- setup ----------------

__global__ void k_zero(const float* __restrict__ We1, const float* __restrict__ ae1,
                       const float* __restrict__ We2, const float* __restrict__ ae2) {
    int i = blockIdx.x * blockDim.x + threadIdx.x;
    if (i < NN) g_cnt[i] = 0;
    if (i < GG * HD) g_pool[i] = ENC_NEGINF;
    if (blockIdx.x == 0 && threadIdx.x < 32) {
        int t = threadIdx.x;
        const float* We = (t < 16) ? We1 : We2;
        const float* ae = (t < 16) ? ae1 : ae2;
        int j = t & 15;
        float s = 0.f;
        #pragma unroll 8
        for (int c = 0; c < HD; c++) s += We[j * HD + c] * ae[c];
        g_v[t] = s;
    }
}

__global__ void k_cnt(const int* __restrict__ dst) {
    int i = blockIdx.x * blockDim.x + threadIdx.x;
    if (i < EE) atomicAdd(&g_cnt[dst[i]], 1);
}

__global__ void k_scan1() {
    __shared__ int sh[SCAN_B];
    int t = threadIdx.x;
    int i = blockIdx.x * SCAN_B + t;
    int v = (i < NN) ? g_cnt[i] : 0;
    sh[t] = v;
    __syncthreads();
    for (int off = 1; off < SCAN_B; off <<= 1) {
        int x = (t >= off) ? sh[t - off] : 0;
        __syncthreads();
        sh[t] += x;
        __syncthreads();
    }
    if (i < NN) g_rs[i] = sh[t] - v;
    if (t == SCAN_B - 1) g_bsum[blockIdx.x] = sh[t];
}

__global__ void k_scan2() {          // single-warp scan over SCAN_G block sums
    int lane = threadIdx.x;
    int base = lane * 4;
    int v0 = (base + 0 < SCAN_G) ? g_bsum[base + 0] : 0;
    int v1 = (base + 1 < SCAN_G) ? g_bsum[base + 1] : 0;
    int v2 = (base + 2 < SCAN_G) ? g_bsum[base + 2] : 0;
    int v3 = (base + 3 < SCAN_G) ? g_bsum[base + 3] : 0;
    int e1 = v0, e2 = v0 + v1, e3 = v0 + v1 + v2;
    int tot = e3 + v3;
    int x = tot;
    #pragma unroll
    for (int off = 1; off < 32; off <<= 1) {
        int y = __shfl_up_sync(0xffffffffu, x, off);
        if (lane >= off) x += y;
    }
    int excl = x - tot;
    if (base + 0 < SCAN_G) g_boff[base + 0] = excl;
    if (base + 1 < SCAN_G) g_boff[base + 1] = excl + e1;
    if (base + 2 < SCAN_G) g_boff[base + 2] = excl + e2;
    if (base + 3 < SCAN_G) g_boff[base + 3] = excl + e3;
}

__global__ void k_scan3() {
    int i = blockIdx.x * SCAN_B + threadIdx.x;
    if (i < NN) {
        int rs = g_rs[i] + g_boff[blockIdx.x];
        g_rs[i] = rs;
        g_cur[i] = rs;
        g_dinv[i] = rsqrtf((float)(g_cnt[i] + 1));
    }
    if (i == 0) g_rs[NN] = EE;
}

__global__ void k_scatter(const float* __restrict__ ea,
                          const int* __restrict__ src, const int* __restrict__ dst) {
    int i = blockIdx.x * blockDim.x + threadIdx.x;
    if (i >= EE) return;
    const float4* p = (const float4*)(ea + (size_t)i * 16);
    float e[16];
    #pragma unroll
    for (int k = 0; k < 4; k++) {
        float4 q = p[k];
        e[4*k] = q.x; e[4*k+1] = q.y; e[4*k+2] = q.z; e[4*k+3] = q.w;
    }
    float s1 = 0.f, s2 = 0.f;
    #pragma unroll
    for (int k = 0; k < 16; k++) { s1 += e[k] * g_v[k]; s2 += e[k] * g_v[16 + k]; }
    int d = dst[i];
    int pos = atomicAdd(&g_cur[d], 1);
    __half2 h = __floats2half2_rn(s1, s2);
    c_src[pos] = src[i];
    c_es[pos]  = *reinterpret_cast<unsigned*>(&h);
}

// ---------------- tensor-core GEMM ----------------
// hw[N,64](half) = X[N,KD] @ W[KD,64];  MODE 0: rows scaled by dinv.
// block: 256 thr = 8 warps; tile 64 rows x 64 cols; warp = 16 rows x 32 cols.
template <int KD, int MODE>
__global__ void k_gemm(const float* __restrict__ Xext, const float* __restrict__ W,
                       int useInternal) {
    const float* X = useInternal ? g_hA : Xext;
    __shared__ __half Xs[64][KD + 8];
    __shared__ __half Ws[KD][72];
    int tid = threadIdx.x;
    int node0 = blockIdx.x * 64;

    for (int i = tid; i < 64 * KD; i += 256) {
        int r = i / KD, k = i % KD;
        float v = (node0 + r < NN) ? X[(size_t)(node0 + r) * KD + k] : 0.f;
        Xs[r][k] = __float2half(v);
    }
    for (int i = tid; i < KD * 64; i += 256) {
        int k = i >> 6, n = i & 63;
        Ws[k][n] = __float2half(W[k * 64 + n]);
    }
    __syncthreads();

    int wid  = tid >> 5;
    int lane = tid & 31;
    int rt = wid >> 1;            // row tile 0..3
    int ch = wid & 1;             // col half 0..1
    int g  = lane >> 2;
    int t2 = (lane & 3) * 2;
    int row0 = rt * 16;

    float c[4][4];
    #pragma unroll
    for (int nt = 0; nt < 4; nt++)
        #pragma unroll
        for (int q = 0; q < 4; q++) c[nt][q] = 0.f;

    #pragma unroll
    for (int ks = 0; ks < KD / 16; ks++) {
        int k0 = ks * 16;
        unsigned a0 = *(const unsigned*)&Xs[row0 + g    ][k0 + t2];
        unsigned a1 = *(const unsigned*)&Xs[row0 + g + 8][k0 + t2];
        unsigned a2 = *(const unsigned*)&Xs[row0 + g    ][k0 + t2 + 8];
        unsigned a3 = *(const unsigned*)&Xs[row0 + g + 8][k0 + t2 + 8];
        #pragma unroll
        for (int nt = 0; nt < 4; nt++) {
            int n0 = ch * 32 + nt * 8 + g;
            __half2 b0h = __halves2half2(Ws[k0 + t2    ][n0], Ws[k0 + t2 + 1][n0]);
            __half2 b1h = __halves2half2(Ws[k0 + t2 + 8][n0], Ws[k0 + t2 + 9][n0]);
            unsigned b0 = *reinterpret_cast<unsigned*>(&b0h);
            unsigned b1 = *reinterpret_cast<unsigned*>(&b1h);
            asm volatile(
                "mma.sync.aligned.m16n8k16.row.col.f32.f16.f16.f32 "
                "{%0,%1,%2,%3}, {%4,%5,%6,%7}, {%8,%9}, {%0,%1,%2,%3};"
                : "+f"(c[nt][0]), "+f"(c[nt][1]), "+f"(c[nt][2]), "+f"(c[nt][3])
                : "r"(a0), "r"(a1), "r"(a2), "r"(a3), "r"(b0), "r"(b1));
        }
    }

    int rowA = node0 + row0 + g;
    int rowB = rowA + 8;
    float scA = 1.f, scB = 1.f;
    if (MODE == 0) {
        scA = (rowA < NN) ? g_dinv[rowA] : 1.f;
        scB = (rowB < NN) ? g_dinv[rowB] : 1.f;
    }
    #pragma unroll
    for (int nt = 0; nt < 4; nt++) {
        int col = ch * 32 + nt * 8 + t2;
        if (rowA < NN)
            *(__half2*)&g_hw[(size_t)rowA * 64 + col] = __floats2half2_rn(c[nt][0] * scA, c[nt][1] * scA);
        if (rowB < NN)
            *(__half2*)&g_hw[(size_t)rowB * 64 + col] = __floats2half2_rn(c[nt][2] * scB, c[nt][3] * scB);
    }
}

// per-node a_s/a_d dots from g_hw (warp per node)
__global__ void k_att(const float* __restrict__ att_s, const float* __restrict__ att_d) {
    int node = blockIdx.x * 8 + (threadIdx.x >> 5);
    int lane = threadIdx.x & 31;
    if (node >= NN) return;
    __half2 hv = ((const __half2*)(g_hw + (size_t)node * 64))[lane];
    float2 f = __half22float2(hv);
    float2 av = ((const float2*)att_s)[lane];
    float2 dv = ((const float2*)att_d)[lane];
    float s = f.x * av.x + f.y * av.y;
    float d = f.x * dv.x + f.y * dv.y;
    #pragma unroll
    for (int o = 16; o; o >>= 1) {
        s += __shfl_down_sync(0xffffffffu, s, o);
        d += __shfl_down_sync(0xffffffffu, d, o);
    }
    if (lane == 0) { g_as[node] = s; g_ad[node] = d; }
}

// ---------------- gathers ----------------

__device__ __forceinline__ float2 hwrow(int s, int lane) {
    __half2 v = *((const __half2*)(g_hw + (size_t)s * 64) + lane);
    return __half22float2(v);
}

// GCN: warp per node; chunk of 32 srcs loaded lane-parallel, shfl-broadcast
__global__ void k_gcn_node(const float* __restrict__ b) {
    int node = blockIdx.x * 8 + (threadIdx.x >> 5);
    int lane = threadIdx.x & 31;
    if (node >= NN) return;
    int rs = g_rs[node], re = g_rs[node + 1];
    float a0 = 0.f, a1 = 0.f;
    for (int jb = rs; jb < re; jb += 32) {
        int n = re - jb; if (n > 32) n = 32;
        int s_l = (lane < n) ? c_src[jb + lane] : 0;
        #pragma unroll 4
        for (int j = 0; j < n; j++) {
            int s = __shfl_sync(0xffffffffu, s_l, j);
            float2 f = hwrow(s, lane);
            a0 += f.x; a1 += f.y;
        }
    }
    float2 fs = hwrow(node, lane);
    a0 += fs.x; a1 += fs.y;
    float di = g_dinv[node];
    float2 bb = ((const float2*)b)[lane];
    float2 o;
    o.x = fmaxf(a0 * di + bb.x, 0.f);
    o.y = fmaxf(a1 * di + bb.y, 0.f);
    ((float2*)(g_hA + (size_t)node * 64))[lane] = o;
}

// GAT: warp per node; lane-parallel score/exp, shfl-broadcast aggregation
template <int LAYER>
__global__ void k_gat_node(const float* __restrict__ b) {
    int node = blockIdx.x * 8 + (threadIdx.x >> 5);
    int lane = threadIdx.x & 31;
    if (node >= NN) return;
    int rs = g_rs[node], re = g_rs[node + 1];
    float ad_n = g_ad[node];
    float a0 = 0.f, a1 = 0.f, den_l = 0.f, es_l = 0.f;
    for (int jb = rs; jb < re; jb += 32) {
        int n = re - jb; if (n > 32) n = 32;
        int s_l = 0; float x_l = 0.f;
        if (lane < n) {
            s_l = c_src[jb + lane];
            unsigned eu = c_es[jb + lane];
            __half2 eh = *reinterpret_cast<__half2*>(&eu);
            float e = (LAYER == 1) ? __low2float(eh) : __high2float(eh);
            x_l = __expf(lrelu(g_as[s_l] + ad_n + e));
            den_l += x_l;
            es_l  += e;
        }
        #pragma unroll 4
        for (int j = 0; j < n; j++) {
            int s   = __shfl_sync(0xffffffffu, s_l, j);
            float x = __shfl_sync(0xffffffffu, x_l, j);
            float2 f = hwrow(s, lane);
            a0 += x * f.x; a1 += x * f.y;
        }
    }
    // reduce den and es-sum across warp
    #pragma unroll
    for (int o = 16; o; o >>= 1) {
        den_l += __shfl_xor_sync(0xffffffffu, den_l, o);
        es_l  += __shfl_xor_sync(0xffffffffu, es_l, o);
    }
    // self loop: edge score = mean of incoming es
    float cnt = (float)(re - rs);
    float x = __expf(lrelu(g_as[node] + ad_n + es_l / fmaxf(cnt, 1.f)));
    float den = den_l + x;
    float2 fs = hwrow(node, lane);
    a0 += x * fs.x; a1 += x * fs.y;
    float inv = 1.f / den;
    float2 bb = ((const float2*)b)[lane];
    float2 o;
    o.x = fmaxf(a0 * inv + bb.x, 0.f);
    o.y = fmaxf(a1 * inv + bb.y, 0.f);
    ((float2*)(g_hA + (size_t)node * 64))[lane] = o;
}

// ---------------- pool + head ----------------

__global__ void k_pool(const int* __restrict__ batch) {
    int c   = threadIdx.x & 63;
    int grp = threadIdx.x >> 6;
    int n0  = blockIdx.x * 64 + grp * 16;
    if (n0 >= NN) return;
    int curg = batch[n0];
    float m = -3.402823466e+38f;
    for (int k = 0; k < 16; k++) {
        int n = n0 + k;
        if (n >= NN) break;
        int bg = batch[n];
        if (bg != curg) {
            atomicMax(&g_pool[curg * 64 + c], encf(m));
            m = -3.402823466e+38f;
            curg = bg;
        }
        m = fmaxf(m, g_hA[(size_t)n * 64 + c]);
    }
    atomicMax(&g_pool[curg * 64 + c], encf(m));
}

__global__ void k_fc(const float* __restrict__ W1, const float* __restrict__ b1,
                     const float* __restrict__ W2, const float* __restrict__ b2,
                     float* __restrict__ out) {
    __shared__ float t0[64], t1[64];
    int g = blockIdx.x, c = threadIdx.x;
    t0[c] = decf(g_pool[g * 64 + c]);
    __syncthreads();
    float s = 0.f;
    #pragma unroll 8
    for (int k = 0; k < 64; k++) s += t0[k] * W1[k * 64 + c];
    t1[c] = fmaxf(s + b1[c], 0.f);
    __syncthreads();
    float o = 0.f;
    #pragma unroll 8
    for (int k = 0; k < 64; k++) o += t1[k] * W2[k * 64 + c];
    out[g * 64 + c] = o + b2[c];
}

// ---------------- launch ----------------
extern "C" void kernel_launch(void* const* d_in, const int* in_sizes, int n_in,
                              void* d_out, int out_size) {
    const float* x     = (const float*)d_in[0];
    const int*   ei    = (const int*)  d_in[1];
    const float* ea    = (const float*)d_in[2];
    const int*   batch = (const int*)  d_in[3];
    const float* W_gcn = (const float*)d_in[4];
    const float* b_gcn = (const float*)d_in[5];
    const float* W1    = (const float*)d_in[6];
    const float* We1   = (const float*)d_in[7];
    const float* as1   = (const float*)d_in[8];
    const float* ad1   = (const float*)d_in[9];
    const float* ae1   = (const float*)d_in[10];
    const float* b1    = (const float*)d_in[11];
    const float* W2    = (const float*)d_in[12];
    const float* We2   = (const float*)d_in[13];
    const float* as2   = (const float*)d_in[14];
    const float* ad2   = (const float*)d_in[15];
    const float* ae2   = (const float*)d_in[16];
    const float* b2    = (const float*)d_in[17];
    const float* Wf1   = (const float*)d_in[18];
    const float* bf1   = (const float*)d_in[19];
    const float* Wf2   = (const float*)d_in[20];
    const float* bf2   = (const float*)d_in[21];
    float* out = (float*)d_out;

    const int* src = ei;
    const int* dst = ei + EE;

    const int TB = 256;
    const int gE    = (EE + TB - 1) / TB;
    const int gGemm = (NN + 63) / 64;         // 1563
    const int gNode = (NN + 7) / 8;           // 12500

    k_zero<<<(GG * HD + TB - 1) / TB, TB>>>(We1, ae1, We2, ae2);
    k_cnt<<<gE, TB>>>(dst);
    k_scan1<<<SCAN_G, SCAN_B>>>();
    k_scan2<<<1, 32>>>();
    k_scan3<<<SCAN_G, SCAN_B>>>();
    k_scatter<<<gE, TB>>>(ea, src, dst);

    // GCN
    k_gemm<128, 0><<<gGemm, TB>>>(x, W_gcn, 0);
    k_gcn_node<<<gNode, TB>>>(b_gcn);

    // GAT 1
    k_gemm<64, 1><<<gGemm, TB>>>(nullptr, W1, 1);
    k_att<<<gNode, TB>>>(as1, ad1);
    k_gat_node<1><<<gNode, TB>>>(b1);

    // GAT 2
    k_gemm<64, 1><<<gGemm, TB>>>(nullptr, W2, 1);
    k_att<<<gNode, TB>>>(as2, ad2);
    k_gat_node<2><<<gNode, TB>>>(b2);

    // pool + MLP head
    k_pool<<<(NN + 63) / 64, TB>>>(batch);
    k_fc<<<GG, 64>>>(Wf1, bf1, Wf2, bf2, out);
}

// round 6
// speedup vs baseline: 2.6171x; 1.0592x over previous
#include <cuda_runtime.h>
#include <cuda_fp16.h>

#define NN 100000
#define EE 1600000
#define GG 2048
#define HD 64
#define SCAN_B 1024
#define SCAN_G ((NN + SCAN_B - 1) / SCAN_B)   // 98

// ---------------- scratch ----------------
__device__ float    g_hA[NN * HD];
__device__ __half   g_hw[NN * HD];
__device__ float    g_dinv[NN];
__device__ float    g_as[NN], g_ad[NN];
__device__ int      g_cnt[NN];          // stays zeroed between runs
__device__ int      g_rs[NN + 1];
__device__ int      g_cur[NN];
__device__ int      g_bsum[SCAN_G], g_boff[SCAN_G];
__device__ int      g_tick;             // stays zeroed between runs
__device__ int      c_src[EE];
__device__ unsigned c_es[EE];
__device__ unsigned g_pool[GG * HD];    // re-armed by k_fc each run (0 also safe on run 1)
__device__ float    g_v[32];

__device__ __forceinline__ unsigned encf(float f) {
    unsigned u = __float_as_uint(f);
    return (u & 0x80000000u) ? ~u : (u | 0x80000000u);
}
__device__ __forceinline__ float decf(unsigned u) {
    return __uint_as_float((u & 0x80000000u) ? (u & 0x7fffffffu) : ~u);
}
#define ENC_NEGINF 0x007fffffu

__device__ __forceinline__ float lrelu(float a) { return (a > 0.f) ? a : 0.2f * a; }

// ---------------- setup ----------------

// count in-degrees; block 0 also computes g_v = We@ae for both layers
__global__ void k_cnt(const int* __restrict__ dst,
                      const float* __restrict__ We1, const float* __restrict__ ae1,
                      const float* __restrict__ We2, const float* __restrict__ ae2) {
    int i = blockIdx.x * blockDim.x + threadIdx.x;
    if (blockIdx.x == 0 && threadIdx.x < 32) {
        int t = threadIdx.x;
        const float* We = (t < 16) ? We1 : We2;
        const float* ae = (t < 16) ? ae1 : ae2;
        int j = t & 15;
        float s = 0.f;
        #pragma unroll 8
        for (int c = 0; c < HD; c++) s += We[j * HD + c] * ae[c];
        g_v[t] = s;
    }
    if (i < EE) atomicAdd(&g_cnt[dst[i]], 1);
}

// block-level scan + (last block) cross-block scan of block sums
__global__ void k_scan1() {
    __shared__ int sh[SCAN_B];
    __shared__ int is_last;
    int t = threadIdx.x;
    int i = blockIdx.x * SCAN_B + t;
    int v = (i < NN) ? g_cnt[i] : 0;
    sh[t] = v;
    __syncthreads();
    for (int off = 1; off < SCAN_B; off <<= 1) {
        int x = (t >= off) ? sh[t - off] : 0;
        __syncthreads();
        sh[t] += x;
        __syncthreads();
    }
    if (i < NN) g_rs[i] = sh[t] - v;
    if (t == SCAN_B - 1) g_bsum[blockIdx.x] = sh[t];
    __threadfence();
    __syncthreads();
    if (t == 0) is_last = (atomicAdd(&g_tick, 1) == SCAN_G - 1) ? 1 : 0;
    __syncthreads();
    if (is_last && t < 32) {
        int lane = t;
        int base = lane * 4;
        int v0 = (base + 0 < SCAN_G) ? g_bsum[base + 0] : 0;
        int v1 = (base + 1 < SCAN_G) ? g_bsum[base + 1] : 0;
        int v2 = (base + 2 < SCAN_G) ? g_bsum[base + 2] : 0;
        int v3 = (base + 3 < SCAN_G) ? g_bsum[base + 3] : 0;
        int e1 = v0, e2 = v0 + v1, e3 = v0 + v1 + v2;
        int tot = e3 + v3;
        int x = tot;
        #pragma unroll
        for (int off = 1; off < 32; off <<= 1) {
            int y = __shfl_up_sync(0xffffffffu, x, off);
            if (lane >= off) x += y;
        }
        int excl = x - tot;
        if (base + 0 < SCAN_G) g_boff[base + 0] = excl;
        if (base + 1 < SCAN_G) g_boff[base + 1] = excl + e1;
        if (base + 2 < SCAN_G) g_boff[base + 2] = excl + e2;
        if (base + 3 < SCAN_G) g_boff[base + 3] = excl + e3;
        if (lane == 0) g_tick = 0;   // reset for next run
    }
}

__global__ void k_scan3() {
    int i = blockIdx.x * SCAN_B + threadIdx.x;
    if (i < NN) {
        int cv = g_cnt[i];
        g_cnt[i] = 0;                 // leave zeroed for next run
        int rs = g_rs[i] + g_boff[blockIdx.x];
        g_rs[i] = rs;
        g_cur[i] = rs;
        g_dinv[i] = rsqrtf((float)(cv + 1));
    }
    if (i == 0) g_rs[NN] = EE;
}

__global__ void k_scatter(const float* __restrict__ ea,
                          const int* __restrict__ src, const int* __restrict__ dst) {
    int i = blockIdx.x * blockDim.x + threadIdx.x;
    if (i >= EE) return;
    const float4* p = (const float4*)(ea + (size_t)i * 16);
    float e[16];
    #pragma unroll
    for (int k = 0; k < 4; k++) {
        float4 q = p[k];
        e[4*k] = q.x; e[4*k+1] = q.y; e[4*k+2] = q.z; e[4*k+3] = q.w;
    }
    float s1 = 0.f, s2 = 0.f;
    #pragma unroll
    for (int k = 0; k < 16; k++) { s1 += e[k] * g_v[k]; s2 += e[k] * g_v[16 + k]; }
    int d = dst[i];
    int pos = atomicAdd(&g_cur[d], 1);
    __half2 h = __floats2half2_rn(s1, s2);
    c_src[pos] = src[i];
    c_es[pos]  = *reinterpret_cast<unsigned*>(&h);
}

// ---------------- tensor-core GEMM ----------------
// hw[N,64](half) = X[N,KD] @ W[KD,64]
// MODE 0 (GCN): rows scaled by dinv.  MODE 1 (GAT): epilogue computes a_s/a_d.
template <int KD, int MODE>
__global__ void k_gemm(const float* __restrict__ Xext, const float* __restrict__ W,
                       const float* __restrict__ att_s, const float* __restrict__ att_d,
                       int useInternal) {
    const float* X = useInternal ? g_hA : Xext;
    __shared__ __half Xs[64][KD + 8];
    __shared__ __half Ws[KD][72];
    __shared__ float sred[64], dred[64];
    int tid = threadIdx.x;
    int node0 = blockIdx.x * 64;

    for (int i = tid; i < 64 * KD; i += 256) {
        int r = i / KD, k = i % KD;
        float v = (node0 + r < NN) ? X[(size_t)(node0 + r) * KD + k] : 0.f;
        Xs[r][k] = __float2half(v);
    }
    for (int i = tid; i < KD * 64; i += 256) {
        int k = i >> 6, n = i & 63;
        Ws[k][n] = __float2half(W[k * 64 + n]);
    }
    if (MODE == 1 && tid < 64) { sred[tid] = 0.f; dred[tid] = 0.f; }
    __syncthreads();

    int wid  = tid >> 5;
    int lane = tid & 31;
    int rt = wid >> 1;
    int ch = wid & 1;
    int g  = lane >> 2;
    int t2 = (lane & 3) * 2;
    int row0 = rt * 16;

    float c[4][4];
    #pragma unroll
    for (int nt = 0; nt < 4; nt++)
        #pragma unroll
        for (int q = 0; q < 4; q++) c[nt][q] = 0.f;

    #pragma unroll
    for (int ks = 0; ks < KD / 16; ks++) {
        int k0 = ks * 16;
        unsigned a0 = *(const unsigned*)&Xs[row0 + g    ][k0 + t2];
        unsigned a1 = *(const unsigned*)&Xs[row0 + g + 8][k0 + t2];
        unsigned a2 = *(const unsigned*)&Xs[row0 + g    ][k0 + t2 + 8];
        unsigned a3 = *(const unsigned*)&Xs[row0 + g + 8][k0 + t2 + 8];
        #pragma unroll
        for (int nt = 0; nt < 4; nt++) {
            int n0 = ch * 32 + nt * 8 + g;
            __half2 b0h = __halves2half2(Ws[k0 + t2    ][n0], Ws[k0 + t2 + 1][n0]);
            __half2 b1h = __halves2half2(Ws[k0 + t2 + 8][n0], Ws[k0 + t2 + 9][n0]);
            unsigned b0 = *reinterpret_cast<unsigned*>(&b0h);
            unsigned b1 = *reinterpret_cast<unsigned*>(&b1h);
            asm volatile(
                "mma.sync.aligned.m16n8k16.row.col.f32.f16.f16.f32 "
                "{%0,%1,%2,%3}, {%4,%5,%6,%7}, {%8,%9}, {%0,%1,%2,%3};"
                : "+f"(c[nt][0]), "+f"(c[nt][1]), "+f"(c[nt][2]), "+f"(c[nt][3])
                : "r"(a0), "r"(a1), "r"(a2), "r"(a3), "r"(b0), "r"(b1));
        }
    }

    int rowA = node0 + row0 + g;
    int rowB = rowA + 8;
    float scA = 1.f, scB = 1.f;
    if (MODE == 0) {
        scA = (rowA < NN) ? g_dinv[rowA] : 1.f;
        scB = (rowB < NN) ? g_dinv[rowB] : 1.f;
    }
    #pragma unroll
    for (int nt = 0; nt < 4; nt++) {
        int col = ch * 32 + nt * 8 + t2;
        if (rowA < NN)
            *(__half2*)&g_hw[(size_t)rowA * 64 + col] = __floats2half2_rn(c[nt][0] * scA, c[nt][1] * scA);
        if (rowB < NN)
            *(__half2*)&g_hw[(size_t)rowB * 64 + col] = __floats2half2_rn(c[nt][2] * scB, c[nt][3] * scB);
    }

    if (MODE == 1) {
        // per-row dots with att_s / att_d from register accumulators
        float pAs = 0.f, pAd = 0.f, pBs = 0.f, pBd = 0.f;
        #pragma unroll
        for (int nt = 0; nt < 4; nt++) {
            int col = ch * 32 + nt * 8 + t2;
            float s0 = att_s[col], s1v = att_s[col + 1];
            float d0 = att_d[col], d1v = att_d[col + 1];
            pAs += c[nt][0] * s0 + c[nt][1] * s1v;
            pAd += c[nt][0] * d0 + c[nt][1] * d1v;
            pBs += c[nt][2] * s0 + c[nt][3] * s1v;
            pBd += c[nt][2] * d0 + c[nt][3] * d1v;
        }
        // reduce over the 4 lanes of the quad (same g)
        #pragma unroll
        for (int o = 1; o < 4; o <<= 1) {
            pAs += __shfl_xor_sync(0xffffffffu, pAs, o);
            pAd += __shfl_xor_sync(0xffffffffu, pAd, o);
            pBs += __shfl_xor_sync(0xffffffffu, pBs, o);
            pBd += __shfl_xor_sync(0xffffffffu, pBd, o);
        }
        if ((lane & 3) == 0) {   // one lane per row-half per warp; 2 warps (ch) add
            atomicAdd(&sred[row0 + g],     pAs);
            atomicAdd(&dred[row0 + g],     pAd);
            atomicAdd(&sred[row0 + g + 8], pBs);
            atomicAdd(&dred[row0 + g + 8], pBd);
        }
        __syncthreads();
        if (tid < 64 && node0 + tid < NN) {
            g_as[node0 + tid] = sred[tid];
            g_ad[node0 + tid] = dred[tid];
        }
    }
}

// ---------------- gathers ----------------

__device__ __forceinline__ float2 hwrow(int s, int lane) {
    __half2 v = *((const __half2*)(g_hw + (size_t)s * 64) + lane);
    return __half22float2(v);
}

__global__ void k_gcn_node(const float* __restrict__ b) {
    int node = blockIdx.x * 8 + (threadIdx.x >> 5);
    int lane = threadIdx.x & 31;
    if (node >= NN) return;
    int rs = g_rs[node], re = g_rs[node + 1];
    float a0 = 0.f, a1 = 0.f;
    for (int jb = rs; jb < re; jb += 32) {
        int n = re - jb; if (n > 32) n = 32;
        int s_l = (lane < n) ? c_src[jb + lane] : 0;
        #pragma unroll 8
        for (int j = 0; j < n; j++) {
            int s = __shfl_sync(0xffffffffu, s_l, j);
            float2 f = hwrow(s, lane);
            a0 += f.x; a1 += f.y;
        }
    }
    float2 fs = hwrow(node, lane);
    a0 += fs.x; a1 += fs.y;
    float di = g_dinv[node];
    float2 bb = ((const float2*)b)[lane];
    float2 o;
    o.x = fmaxf(a0 * di + bb.x, 0.f);
    o.y = fmaxf(a1 * di + bb.y, 0.f);
    ((float2*)(g_hA + (size_t)node * 64))[lane] = o;
}

template <int LAYER>
__global__ void k_gat_node(const float* __restrict__ b) {
    int node = blockIdx.x * 8 + (threadIdx.x >> 5);
    int lane = threadIdx.x & 31;
    if (node >= NN) return;
    int rs = g_rs[node], re = g_rs[node + 1];
    float ad_n = g_ad[node];
    float a0 = 0.f, a1 = 0.f, den_l = 0.f, es_l = 0.f;
    for (int jb = rs; jb < re; jb += 32) {
        int n = re - jb; if (n > 32) n = 32;
        int s_l = 0; float x_l = 0.f;
        if (lane < n) {
            s_l = c_src[jb + lane];
            unsigned eu = c_es[jb + lane];
            __half2 eh = *reinterpret_cast<__half2*>(&eu);
            float e = (LAYER == 1) ? __low2float(eh) : __high2float(eh);
            x_l = __expf(lrelu(g_as[s_l] + ad_n + e));
            den_l += x_l;
            es_l  += e;
        }
        #pragma unroll 8
        for (int j = 0; j < n; j++) {
            int s   = __shfl_sync(0xffffffffu, s_l, j);
            float x = __shfl_sync(0xffffffffu, x_l, j);
            float2 f = hwrow(s, lane);
            a0 += x * f.x; a1 += x * f.y;
        }
    }
    #pragma unroll
    for (int o = 16; o; o >>= 1) {
        den_l += __shfl_xor_sync(0xffffffffu, den_l, o);
        es_l  += __shfl_xor_sync(0xffffffffu, es_l, o);
    }
    float cnt = (float)(re - rs);
    float x = __expf(lrelu(g_as[node] + ad_n + es_l / fmaxf(cnt, 1.f)));
    float den = den_l + x;
    float2 fs = hwrow(node, lane);
    a0 += x * fs.x; a1 += x * fs.y;
    float inv = 1.f / den;
    float2 bb = ((const float2*)b)[lane];
    float2 o;
    o.x = fmaxf(a0 * inv + bb.x, 0.f);
    o.y = fmaxf(a1 * inv + bb.y, 0.f);
    ((float2*)(g_hA + (size_t)node * 64))[lane] = o;
}

// ---------------- pool + head ----------------

__global__ void k_pool(const int* __restrict__ batch) {
    int c   = threadIdx.x & 63;
    int grp = threadIdx.x >> 6;
    int n0  = blockIdx.x * 64 + grp * 16;
    if (n0 >= NN) return;
    int curg = batch[n0];
    float m = -3.402823466e+38f;
    for (int k = 0; k < 16; k++) {
        int n = n0 + k;
        if (n >= NN) break;
        int bg = batch[n];
        if (bg != curg) {
            atomicMax(&g_pool[curg * 64 + c], encf(m));
            m = -3.402823466e+38f;
            curg = bg;
        }
        m = fmaxf(m, g_hA[(size_t)n * 64 + c]);
    }
    atomicMax(&g_pool[curg * 64 + c], encf(m));
}

__global__ void k_fc(const float* __restrict__ W1, const float* __restrict__ b1,
                     const float* __restrict__ W2, const float* __restrict__ b2,
                     float* __restrict__ out) {
    __shared__ float t0[64], t1[64];
    int g = blockIdx.x, c = threadIdx.x;
    t0[c] = decf(g_pool[g * 64 + c]);
    g_pool[g * 64 + c] = ENC_NEGINF;     // re-arm for next run
    __syncthreads();
    float s = 0.f;
    #pragma unroll 8
    for (int k = 0; k < 64; k++) s += t0[k] * W1[k * 64 + c];
    t1[c] = fmaxf(s + b1[c], 0.f);
    __syncthreads();
    float o = 0.f;
    #pragma unroll 8
    for (int k = 0; k < 64; k++) o += t1[k] * W2[k * 64 + c];
    out[g * 64 + c] = o + b2[c];
}

// ---------------- launch ----------------
extern "C" void kernel_launch(void* const* d_in, const int* in_sizes, int n_in,
                              void* d_out, int out_size) {
    const float* x     = (const float*)d_in[0];
    const int*   ei    = (const int*)  d_in[1];
    const float* ea    = (const float*)d_in[2];
    const int*   batch = (const int*)  d_in[3];
    const float* W_gcn = (const float*)d_in[4];
    const float* b_gcn = (const float*)d_in[5];
    const float* W1    = (const float*)d_in[6];
    const float* We1   = (const float*)d_in[7];
    const float* as1   = (const float*)d_in[8];
    const float* ad1   = (const float*)d_in[9];
    const float* ae1   = (const float*)d_in[10];
    const float* b1    = (const float*)d_in[11];
    const float* W2    = (const float*)d_in[12];
    const float* We2   = (const float*)d_in[13];
    const float* as2   = (const float*)d_in[14];
    const float* ad2   = (const float*)d_in[15];
    const float* ae2   = (const float*)d_in[16];
    const float* b2    = (const float*)d_in[17];
    const float* Wf1   = (const float*)d_in[18];
    const float* bf1   = (const float*)d_in[19];
    const float* Wf2   = (const float*)d_in[20];
    const float* bf2   = (const float*)d_in[21];
    float* out = (float*)d_out;

    const int* src = ei;
    const int* dst = ei + EE;

    const int TB = 256;
    const int gE    = (EE + TB - 1) / TB;
    const int gGemm = (NN + 63) / 64;
    const int gNode = (NN + 7) / 8;

    k_cnt<<<gE, TB>>>(dst, We1, ae1, We2, ae2);
    k_scan1<<<SCAN_G, SCAN_B>>>();
    k_scan3<<<SCAN_G, SCAN_B>>>();
    k_scatter<<<gE, TB>>>(ea, src, dst);

    // GCN
    k_gemm<128, 0><<<gGemm, TB>>>(x, W_gcn, nullptr, nullptr, 0);
    k_gcn_node<<<gNode, TB>>>(b_gcn);

    // GAT 1
    k_gemm<64, 1><<<gGemm, TB>>>(nullptr, W1, as1, ad1, 1);
    k_gat_node<1><<<gNode, TB>>>(b1);

    // GAT 2
    k_gemm<64, 1><<<gGemm, TB>>>(nullptr, W2, as2, ad2, 1);
    k_gat_node<2><<<gNode, TB>>>(b2);

    // pool + MLP head
    k_pool<<<(NN + 63) / 64, TB>>>(batch);
    k_fc<<<GG, 64>>>(Wf1, bf1, Wf2, bf2, out);
}

// round 7
// speedup vs baseline: 2.6542x; 1.0142x over previous
#include <cuda_runtime.h>
#include <cuda_fp16.h>

#define NN 100000
#define EE 1600000
#define GG 2048
#define HD 64
#define SCAN_B 1024
#define SCAN_G ((NN + SCAN_B - 1) / SCAN_B)   // 98

// ---------------- scratch ----------------
__device__ float    g_hA[NN * HD];
__device__ __half   g_hw[NN * HD];
__device__ float    g_dinv[NN];
__device__ float    g_as[NN], g_ad[NN];
__device__ int      g_cnt[NN];          // stays zeroed between runs
__device__ int      g_rs[NN + 1];
__device__ int      g_cur[NN];
__device__ int      g_bsum[SCAN_G], g_boff[SCAN_G];
__device__ int      g_tick;             // stays zeroed between runs
__device__ uint2    c_pack[EE];         // (src, half2(es1,es2)) CSR-ordered
__device__ unsigned g_pool[GG * HD];    // re-armed by k_fc each run
__device__ float    g_v[32];

__device__ __forceinline__ unsigned encf(float f) {
    unsigned u = __float_as_uint(f);
    return (u & 0x80000000u) ? ~u : (u | 0x80000000u);
}
__device__ __forceinline__ float decf(unsigned u) {
    return __uint_as_float((u & 0x80000000u) ? (u & 0x7fffffffu) : ~u);
}
#define ENC_NEGINF 0x007fffffu

__device__ __forceinline__ float lrelu(float a) { return (a > 0.f) ? a : 0.2f * a; }

// ---------------- setup ----------------

// count in-degrees (int4, 4 edges/thread); block 0 warp 0 computes g_v
__global__ void k_cnt(const int4* __restrict__ dst4,
                      const float* __restrict__ We1, const float* __restrict__ ae1,
                      const float* __restrict__ We2, const float* __restrict__ ae2) {
    int i = blockIdx.x * blockDim.x + threadIdx.x;
    if (blockIdx.x == 0 && threadIdx.x < 32) {
        int t = threadIdx.x;
        const float* We = (t < 16) ? We1 : We2;
        const float* ae = (t < 16) ? ae1 : ae2;
        int j = t & 15;
        float s = 0.f;
        #pragma unroll 8
        for (int c = 0; c < HD; c++) s += We[j * HD + c] * ae[c];
        g_v[t] = s;
    }
    if (i < EE / 4) {
        int4 d = dst4[i];
        atomicAdd(&g_cnt[d.x], 1);
        atomicAdd(&g_cnt[d.y], 1);
        atomicAdd(&g_cnt[d.z], 1);
        atomicAdd(&g_cnt[d.w], 1);
    }
}

// block scan + (last block) cross-block scan of block sums
__global__ void k_scan1() {
    __shared__ int sh[SCAN_B];
    __shared__ int is_last;
    int t = threadIdx.x;
    int i = blockIdx.x * SCAN_B + t;
    int v = (i < NN) ? g_cnt[i] : 0;
    sh[t] = v;
    __syncthreads();
    for (int off = 1; off < SCAN_B; off <<= 1) {
        int x = (t >= off) ? sh[t - off] : 0;
        __syncthreads();
        sh[t] += x;
        __syncthreads();
    }
    if (i < NN) g_rs[i] = sh[t] - v;
    if (t == SCAN_B - 1) g_bsum[blockIdx.x] = sh[t];
    __threadfence();
    __syncthreads();
    if (t == 0) is_last = (atomicAdd(&g_tick, 1) == SCAN_G - 1) ? 1 : 0;
    __syncthreads();
    if (is_last) __threadfence();
    if (is_last && t < 32) {
        int lane = t;
        int base = lane * 4;
        int v0 = (base + 0 < SCAN_G) ? g_bsum[base + 0] : 0;
        int v1 = (base + 1 < SCAN_G) ? g_bsum[base + 1] : 0;
        int v2 = (base + 2 < SCAN_G) ? g_bsum[base + 2] : 0;
        int v3 = (base + 3 < SCAN_G) ? g_bsum[base + 3] : 0;
        int e1 = v0, e2 = v0 + v1, e3 = v0 + v1 + v2;
        int tot = e3 + v3;
        int x = tot;
        #pragma unroll
        for (int off = 1; off < 32; off <<= 1) {
            int y = __shfl_up_sync(0xffffffffu, x, off);
            if (lane >= off) x += y;
        }
        int excl = x - tot;
        if (base + 0 < SCAN_G) g_boff[base + 0] = excl;
        if (base + 1 < SCAN_G) g_boff[base + 1] = excl + e1;
        if (base + 2 < SCAN_G) g_boff[base + 2] = excl + e2;
        if (base + 3 < SCAN_G) g_boff[base + 3] = excl + e3;
        if (lane == 0) g_tick = 0;
    }
}

__global__ void k_scan3() {
    int i = blockIdx.x * SCAN_B + threadIdx.x;
    if (i < NN) {
        int cv = g_cnt[i];
        g_cnt[i] = 0;
        int rs = g_rs[i] + g_boff[blockIdx.x];
        g_rs[i] = rs;
        g_cur[i] = rs;
        g_dinv[i] = rsqrtf((float)(cv + 1));
    }
    if (i == 0) g_rs[NN] = EE;
}

// 2 edges/thread (split halves, both coalesced) for higher MLP
__global__ void k_scatter(const float* __restrict__ ea,
                          const int* __restrict__ src, const int* __restrict__ dst) {
    int i = blockIdx.x * blockDim.x + threadIdx.x;
    if (i >= EE / 2) return;
    int i2 = i + EE / 2;
    const float4* pA = (const float4*)(ea + (size_t)i  * 16);
    const float4* pB = (const float4*)(ea + (size_t)i2 * 16);
    float4 qa0 = pA[0], qa1 = pA[1], qa2 = pA[2], qa3 = pA[3];
    float4 qb0 = pB[0], qb1 = pB[1], qb2 = pB[2], qb3 = pB[3];
    int dA = dst[i], dB = dst[i2];
    int sA = src[i], sB = src[i2];
    float ea_[16], eb_[16];
    ea_[0]=qa0.x; ea_[1]=qa0.y; ea_[2]=qa0.z; ea_[3]=qa0.w;
    ea_[4]=qa1.x; ea_[5]=qa1.y; ea_[6]=qa1.z; ea_[7]=qa1.w;
    ea_[8]=qa2.x; ea_[9]=qa2.y; ea_[10]=qa2.z; ea_[11]=qa2.w;
    ea_[12]=qa3.x; ea_[13]=qa3.y; ea_[14]=qa3.z; ea_[15]=qa3.w;
    eb_[0]=qb0.x; eb_[1]=qb0.y; eb_[2]=qb0.z; eb_[3]=qb0.w;
    eb_[4]=qb1.x; eb_[5]=qb1.y; eb_[6]=qb1.z; eb_[7]=qb1.w;
    eb_[8]=qb2.x; eb_[9]=qb2.y; eb_[10]=qb2.z; eb_[11]=qb2.w;
    eb_[12]=qb3.x; eb_[13]=qb3.y; eb_[14]=qb3.z; eb_[15]=qb3.w;
    float sA1 = 0.f, sA2 = 0.f, sB1 = 0.f, sB2 = 0.f;
    #pragma unroll
    for (int k = 0; k < 16; k++) {
        float v1 = g_v[k], v2 = g_v[16 + k];
        sA1 += ea_[k] * v1; sA2 += ea_[k] * v2;
        sB1 += eb_[k] * v1; sB2 += eb_[k] * v2;
    }
    int posA = atomicAdd(&g_cur[dA], 1);
    int posB = atomicAdd(&g_cur[dB], 1);
    __half2 hA = __floats2half2_rn(sA1, sA2);
    __half2 hB = __floats2half2_rn(sB1, sB2);
    uint2 pkA, pkB;
    pkA.x = (unsigned)sA; pkA.y = *reinterpret_cast<unsigned*>(&hA);
    pkB.x = (unsigned)sB; pkB.y = *reinterpret_cast<unsigned*>(&hB);
    c_pack[posA] = pkA;
    c_pack[posB] = pkB;
}

// ---------------- tensor-core GEMM ----------------
// hw[N,64](half) = X[N,KD] @ W[KD,64];  ATT=1: epilogue computes a_s/a_d.
template <int KD, int ATT>
__global__ void k_gemm(const float* __restrict__ Xext, const float* __restrict__ W,
                       const float* __restrict__ att_s, const float* __restrict__ att_d,
                       int useInternal) {
    const float* X = useInternal ? g_hA : Xext;
    __shared__ __half Xs[64][KD + 8];
    __shared__ __half Ws[KD][72];
    __shared__ float sred[64], dred[64];
    int tid = threadIdx.x;
    int node0 = blockIdx.x * 64;

    for (int i = tid; i < 64 * KD; i += 256) {
        int r = i / KD, k = i % KD;
        float v = (node0 + r < NN) ? X[(size_t)(node0 + r) * KD + k] : 0.f;
        Xs[r][k] = __float2half(v);
    }
    for (int i = tid; i < KD * 64; i += 256) {
        int k = i >> 6, n = i & 63;
        Ws[k][n] = __float2half(W[k * 64 + n]);
    }
    if (ATT && tid < 64) { sred[tid] = 0.f; dred[tid] = 0.f; }
    __syncthreads();

    int wid  = tid >> 5;
    int lane = tid & 31;
    int rt = wid >> 1;
    int ch = wid & 1;
    int g  = lane >> 2;
    int t2 = (lane & 3) * 2;
    int row0 = rt * 16;

    float c[4][4];
    #pragma unroll
    for (int nt = 0; nt < 4; nt++)
        #pragma unroll
        for (int q = 0; q < 4; q++) c[nt][q] = 0.f;

    #pragma unroll
    for (int ks = 0; ks < KD / 16; ks++) {
        int k0 = ks * 16;
        unsigned a0 = *(const unsigned*)&Xs[row0 + g    ][k0 + t2];
        unsigned a1 = *(const unsigned*)&Xs[row0 + g + 8][k0 + t2];
        unsigned a2 = *(const unsigned*)&Xs[row0 + g    ][k0 + t2 + 8];
        unsigned a3 = *(const unsigned*)&Xs[row0 + g + 8][k0 + t2 + 8];
        #pragma unroll
        for (int nt = 0; nt < 4; nt++) {
            int n0 = ch * 32 + nt * 8 + g;
            __half2 b0h = __halves2half2(Ws[k0 + t2    ][n0], Ws[k0 + t2 + 1][n0]);
            __half2 b1h = __halves2half2(Ws[k0 + t2 + 8][n0], Ws[k0 + t2 + 9][n0]);
            unsigned b0 = *reinterpret_cast<unsigned*>(&b0h);
            unsigned b1 = *reinterpret_cast<unsigned*>(&b1h);
            asm volatile(
                "mma.sync.aligned.m16n8k16.row.col.f32.f16.f16.f32 "
                "{%0,%1,%2,%3}, {%4,%5,%6,%7}, {%8,%9}, {%0,%1,%2,%3};"
                : "+f"(c[nt][0]), "+f"(c[nt][1]), "+f"(c[nt][2]), "+f"(c[nt][3])
                : "r"(a0), "r"(a1), "r"(a2), "r"(a3), "r"(b0), "r"(b1));
        }
    }

    int rowA = node0 + row0 + g;
    int rowB = rowA + 8;
    #pragma unroll
    for (int nt = 0; nt < 4; nt++) {
        int col = ch * 32 + nt * 8 + t2;
        if (rowA < NN)
            *(__half2*)&g_hw[(size_t)rowA * 64 + col] = __floats2half2_rn(c[nt][0], c[nt][1]);
        if (rowB < NN)
            *(__half2*)&g_hw[(size_t)rowB * 64 + col] = __floats2half2_rn(c[nt][2], c[nt][3]);
    }

    if (ATT) {
        float pAs = 0.f, pAd = 0.f, pBs = 0.f, pBd = 0.f;
        #pragma unroll
        for (int nt = 0; nt < 4; nt++) {
            int col = ch * 32 + nt * 8 + t2;
            float s0 = att_s[col], s1v = att_s[col + 1];
            float d0 = att_d[col], d1v = att_d[col + 1];
            pAs += c[nt][0] * s0 + c[nt][1] * s1v;
            pAd += c[nt][0] * d0 + c[nt][1] * d1v;
            pBs += c[nt][2] * s0 + c[nt][3] * s1v;
            pBd += c[nt][2] * d0 + c[nt][3] * d1v;
        }
        #pragma unroll
        for (int o = 1; o < 4; o <<= 1) {
            pAs += __shfl_xor_sync(0xffffffffu, pAs, o);
            pAd += __shfl_xor_sync(0xffffffffu, pAd, o);
            pBs += __shfl_xor_sync(0xffffffffu, pBs, o);
            pBd += __shfl_xor_sync(0xffffffffu, pBd, o);
        }
        if ((lane & 3) == 0) {
            atomicAdd(&sred[row0 + g],     pAs);
            atomicAdd(&dred[row0 + g],     pAd);
            atomicAdd(&sred[row0 + g + 8], pBs);
            atomicAdd(&dred[row0 + g + 8], pBd);
        }
        __syncthreads();
        if (tid < 64 && node0 + tid < NN) {
            g_as[node0 + tid] = sred[tid];
            g_ad[node0 + tid] = dred[tid];
        }
    }
}

// ---------------- gathers ----------------

__device__ __forceinline__ float2 hwrow(int s, int lane) {
    __half2 v = *((const __half2*)(g_hw + (size_t)s * 64) + lane);
    return __half22float2(v);
}

// GCN: dinv[src] applied per edge (lane-parallel load, shfl broadcast)
__global__ void k_gcn_node(const float* __restrict__ b) {
    int node = blockIdx.x * 8 + (threadIdx.x >> 5);
    int lane = threadIdx.x & 31;
    if (node >= NN) return;
    int rs = g_rs[node], re = g_rs[node + 1];
    float a0 = 0.f, a1 = 0.f;
    for (int jb = rs; jb < re; jb += 32) {
        int n = re - jb; if (n > 32) n = 32;
        int s_l = 0; float w_l = 0.f;
        if (lane < n) {
            s_l = (int)c_pack[jb + lane].x;
            w_l = g_dinv[s_l];
        }
        #pragma unroll 8
        for (int j = 0; j < n; j++) {
            int s   = __shfl_sync(0xffffffffu, s_l, j);
            float w = __shfl_sync(0xffffffffu, w_l, j);
            float2 f = hwrow(s, lane);
            a0 += w * f.x; a1 += w * f.y;
        }
    }
    float di = g_dinv[node];
    float2 fs = hwrow(node, lane);
    a0 += di * fs.x; a1 += di * fs.y;
    float2 bb = ((const float2*)b)[lane];
    float2 o;
    o.x = fmaxf(a0 * di + bb.x, 0.f);
    o.y = fmaxf(a1 * di + bb.y, 0.f);
    ((float2*)(g_hA + (size_t)node * 64))[lane] = o;
}

template <int LAYER>
__global__ void k_gat_node(const float* __restrict__ b) {
    int node = blockIdx.x * 8 + (threadIdx.x >> 5);
    int lane = threadIdx.x & 31;
    if (node >= NN) return;
    int rs = g_rs[node], re = g_rs[node + 1];
    float ad_n = g_ad[node];
    float a0 = 0.f, a1 = 0.f, den_l = 0.f, es_l = 0.f;
    for (int jb = rs; jb < re; jb += 32) {
        int n = re - jb; if (n > 32) n = 32;
        int s_l = 0; float x_l = 0.f;
        if (lane < n) {
            uint2 q = c_pack[jb + lane];
            s_l = (int)q.x;
            __half2 eh = *reinterpret_cast<__half2*>(&q.y);
            float e = (LAYER == 1) ? __low2float(eh) : __high2float(eh);
            x_l = __expf(lrelu(g_as[s_l] + ad_n + e));
            den_l += x_l;
            es_l  += e;
        }
        #pragma unroll 8
        for (int j = 0; j < n; j++) {
            int s   = __shfl_sync(0xffffffffu, s_l, j);
            float x = __shfl_sync(0xffffffffu, x_l, j);
            float2 f = hwrow(s, lane);
            a0 += x * f.x; a1 += x * f.y;
        }
    }
    #pragma unroll
    for (int o = 16; o; o >>= 1) {
        den_l += __shfl_xor_sync(0xffffffffu, den_l, o);
        es_l  += __shfl_xor_sync(0xffffffffu, es_l, o);
    }
    float cnt = (float)(re - rs);
    float x = __expf(lrelu(g_as[node] + ad_n + es_l / fmaxf(cnt, 1.f)));
    float den = den_l + x;
    float2 fs = hwrow(node, lane);
    a0 += x * fs.x; a1 += x * fs.y;
    float inv = 1.f / den;
    float2 bb = ((const float2*)b)[lane];
    float2 o;
    o.x = fmaxf(a0 * inv + bb.x, 0.f);
    o.y = fmaxf(a1 * inv + bb.y, 0.f);
    ((float2*)(g_hA + (size_t)node * 64))[lane] = o;
}

// ---------------- pool + head ----------------

__global__ void k_pool(const int* __restrict__ batch) {
    int c   = threadIdx.x & 63;
    int grp = threadIdx.x >> 6;
    int n0  = blockIdx.x * 64 + grp * 16;
    if (n0 >= NN) return;
    int curg = batch[n0];
    float m = -3.402823466e+38f;
    for (int k = 0; k < 16; k++) {
        int n = n0 + k;
        if (n >= NN) break;
        int bg = batch[n];
        if (bg != curg) {
            atomicMax(&g_pool[curg * 64 + c], encf(m));
            m = -3.402823466e+38f;
            curg = bg;
        }
        m = fmaxf(m, g_hA[(size_t)n * 64 + c]);
    }
    atomicMax(&g_pool[curg * 64 + c], encf(m));
}

__global__ void k_fc(const float* __restrict__ W1, const float* __restrict__ b1,
                     const float* __restrict__ W2, const float* __restrict__ b2,
                     float* __restrict__ out) {
    __shared__ float t0[64], t1[64];
    int g = blockIdx.x, c = threadIdx.x;
    t0[c] = decf(g_pool[g * 64 + c]);
    g_pool[g * 64 + c] = ENC_NEGINF;
    __syncthreads();
    float s = 0.f;
    #pragma unroll 8
    for (int k = 0; k < 64; k++) s += t0[k] * W1[k * 64 + c];
    t1[c] = fmaxf(s + b1[c], 0.f);
    __syncthreads();
    float o = 0.f;
    #pragma unroll 8
    for (int k = 0; k < 64; k++) o += t1[k] * W2[k * 64 + c];
    out[g * 64 + c] = o + b2[c];
}

// ---------------- launch ----------------
extern "C" void kernel_launch(void* const* d_in, const int* in_sizes, int n_in,
                              void* d_out, int out_size) {
    const float* x     = (const float*)d_in[0];
    const int*   ei    = (const int*)  d_in[1];
    const float* ea    = (const float*)d_in[2];
    const int*   batch = (const int*)  d_in[3];
    const float* W_gcn = (const float*)d_in[4];
    const float* b_gcn = (const float*)d_in[5];
    const float* W1    = (const float*)d_in[6];
    const float* We1   = (const float*)d_in[7];
    const float* as1   = (const float*)d_in[8];
    const float* ad1   = (const float*)d_in[9];
    const float* ae1   = (const float*)d_in[10];
    const float* b1    = (const float*)d_in[11];
    const float* W2    = (const float*)d_in[12];
    const float* We2   = (const float*)d_in[13];
    const float* as2   = (const float*)d_in[14];
    const float* ad2   = (const float*)d_in[15];
    const float* ae2   = (const float*)d_in[16];
    const float* b2    = (const float*)d_in[17];
    const float* Wf1   = (const float*)d_in[18];
    const float* bf1   = (const float*)d_in[19];
    const float* Wf2   = (const float*)d_in[20];
    const float* bf2   = (const float*)d_in[21];
    float* out = (float*)d_out;

    const int* src = ei;
    const int* dst = ei + EE;

    const int TB = 256;
    const int gGemm = (NN + 63) / 64;
    const int gNode = (NN + 7) / 8;

    // fork: GCN GEMM (independent of CSR build) on side stream
    cudaStream_t s2;
    cudaEvent_t evA, evB;
    cudaStreamCreateWithFlags(&s2, cudaStreamNonBlocking);
    cudaEventCreateWithFlags(&evA, cudaEventDisableTiming);
    cudaEventCreateWithFlags(&evB, cudaEventDisableTiming);

    cudaEventRecord(evA, 0);
    cudaStreamWaitEvent(s2, evA, 0);
    k_gemm<128, 0><<<gGemm, TB, 0, s2>>>(x, W_gcn, nullptr, nullptr, 0);
    cudaEventRecord(evB, s2);

    // CSR build on main stream
    k_cnt<<<(EE / 4 + TB - 1) / TB, TB>>>((const int4*)dst, We1, ae1, We2, ae2);
    k_scan1<<<SCAN_G, SCAN_B>>>();
    k_scan3<<<SCAN_G, SCAN_B>>>();
    k_scatter<<<(EE / 2 + TB - 1) / TB, TB>>>(ea, src, dst);

    cudaStreamWaitEvent(0, evB, 0);

    // GCN aggregate
    k_gcn_node<<<gNode, TB>>>(b_gcn);

    // GAT 1
    k_gemm<64, 1><<<gGemm, TB>>>(nullptr, W1, as1, ad1, 1);
    k_gat_node<1><<<gNode, TB>>>(b1);

    // GAT 2
    k_gemm<64, 1><<<gGemm, TB>>>(nullptr, W2, as2, ad2, 1);
    k_gat_node<2><<<gNode, TB>>>(b2);

    // pool + head
    k_pool<<<(NN + 63) / 64, TB>>>(batch);
    k_fc<<<GG, 64>>>(Wf1, bf1, Wf2, bf2, out);

    cudaStreamDestroy(s2);
    cudaEventDestroy(evA);
    cudaEventDestroy(evB);
}